// round 12
// baseline (speedup 1.0000x reference)
#include <cuda_runtime.h>
#include <math.h>
#include <cstdint>

#define B_   2
#define S_   2048
#define C_   1024
#define H_   16
#define DH_  64
#define M_   (B_ * S_)       // 4096 rows

// ---- scratch (device globals; no allocation allowed) ----
__device__ float g_Q[M_ * C_];           // tf32-rounded (GEMM epilogue)
__device__ float g_K[M_ * C_];           // tf32-rounded (GEMM epilogue)
__device__ float g_V[M_ * C_];           // exact fp32
__device__ float g_A[M_ * C_];           // attention output (tf32-rounded)
__device__ float g_X[M_ * C_];           // tf32-rounded x
__device__ float g_Wt[4 * C_ * C_];      // tf32-rounded weights
__device__ float g_m1[B_ * H_ * S_];     // full-row max of scores (already /8)
__device__ float g_vs[B_ * H_ * DH_];    // sum over all keys of V per (b,h)
__device__ float g_vsp[B_ * H_ * 8 * DH_]; // vsum partials

__device__ __forceinline__ unsigned f2tf(float x) {
    unsigned r;
    asm("cvt.rna.tf32.f32 %0, %1;" : "=r"(r) : "f"(x));
    return r;
}

__device__ __forceinline__ uint32_t s2u(const void* p) {
    uint32_t a;
    asm("{ .reg .u64 t; cvta.to.shared.u64 t, %1; cvt.u32.u64 %0, t; }"
        : "=r"(a) : "l"(p));
    return a;
}

__device__ __forceinline__ void cp16(uint32_t d, const void* s) {
    asm volatile("cp.async.cg.shared.global [%0], [%1], 16;" :: "r"(d), "l"(s));
}
#define CP_COMMIT() asm volatile("cp.async.commit_group;" ::: "memory")
#define CP_WAIT2()  asm volatile("cp.async.wait_group 2;" ::: "memory")

#define MMA_TF32(c, a, b)                                                     \
    asm volatile(                                                             \
        "mma.sync.aligned.m16n8k8.row.col.f32.tf32.tf32.f32 "                 \
        "{%0,%1,%2,%3},{%4,%5,%6,%7},{%8,%9},{%0,%1,%2,%3};"                  \
        : "+f"((c)[0]), "+f"((c)[1]), "+f"((c)[2]), "+f"((c)[3])              \
        : "r"((a)[0]), "r"((a)[1]), "r"((a)[2]), "r"((a)[3]),                 \
          "r"((b)[0]), "r"((b)[1]))

// ============================================================================
// Fused tf32 rounding: x (1M float4) then Wq,Wk,Wv,Wo (256K float4 each).
// ============================================================================
__global__ __launch_bounds__(256) void round_all(
    const float* __restrict__ x,
    const float* __restrict__ W0, const float* __restrict__ W1,
    const float* __restrict__ W2, const float* __restrict__ W3,
    float* __restrict__ X, float* __restrict__ Wt)
{
    const int i = blockIdx.x * 256 + threadIdx.x;   // 0 .. 2M-1 float4
    if (i < (M_ * C_ / 4)) {
        float4 v = ((const float4*)x)[i];
        uint4 t;
        t.x = f2tf(v.x); t.y = f2tf(v.y); t.z = f2tf(v.z); t.w = f2tf(v.w);
        ((uint4*)X)[i] = t;
    } else {
        const int w = i - (M_ * C_ / 4);
        const int z = w >> 18;
        const int j = w & ((1 << 18) - 1);
        const float* src = (z == 0) ? W0 : (z == 1) ? W1 : (z == 2) ? W2 : W3;
        float* dst = Wt + (size_t)z * C_ * C_;
        float4 v = ((const float4*)src)[j];
        uint4 t;
        t.x = f2tf(v.x); t.y = f2tf(v.y); t.z = f2tf(v.z); t.w = f2tf(v.w);
        ((uint4*)dst)[j] = t;
    }
}

// ============================================================================
// cp.async 3-stage tf32 GEMM (R9 winner) + optional tf32-rounded epilogue
// ============================================================================
#define AS_WORDS (128 * 36)
#define BS_WORDS (32 * 128)
#define GEMM_SMEM_BYTES (3 * (AS_WORDS + BS_WORDS) * 4)

__device__ __forceinline__ void issue_tile(
    const float* __restrict__ A, const float* __restrict__ B,
    int K, int N, int bm, int bn, int kb,
    uint32_t sbase, int stage, int tid)
{
#pragma unroll
    for (int u = 0; u < 4; ++u) {
        const int f = tid + 256 * u;
        const int row = f >> 3;
        const int k4 = (f & 7) * 4;
        cp16(sbase + (uint32_t)(stage * AS_WORDS + row * 36 + k4) * 4,
             A + (size_t)(bm + row) * K + kb + k4);
    }
    const int bk = tid >> 3;
    const int n0 = (tid & 7) * 16;
    const unsigned sw = (bk & 3) << 3;
#pragma unroll
    for (int j = 0; j < 4; ++j) {
        cp16(sbase + (uint32_t)(3 * AS_WORDS + stage * BS_WORDS + bk * 128 +
                                ((n0 + j * 4) ^ sw)) * 4,
             B + (size_t)(kb + bk) * N + bn + n0 + j * 4);
    }
}

__device__ __forceinline__ void gemm_ca_body(
    const float* __restrict__ A, const float* __restrict__ B,
    float* __restrict__ C, int N, int K, bool round_out)
{
    extern __shared__ unsigned smbuf[];
    const uint32_t sbase = s2u(smbuf);

    const int tid = threadIdx.x;
    const int bm = blockIdx.y * 128;
    const int bn = blockIdx.x * 128;

    const int wid  = tid >> 5;
    const int lane = tid & 31;
    const int g    = lane >> 2;
    const int tig  = lane & 3;
    const int warpM = wid >> 1;
    const int warpN = wid & 1;
    const unsigned swz = tig << 3;

    float c[2][8][4];
#pragma unroll
    for (int i = 0; i < 2; ++i)
#pragma unroll
        for (int j = 0; j < 8; ++j)
#pragma unroll
            for (int r = 0; r < 4; ++r) c[i][j][r] = 0.f;

    const int nt = K >> 5;

    issue_tile(A, B, K, N, bm, bn, 0,  sbase, 0, tid); CP_COMMIT();
    issue_tile(A, B, K, N, bm, bn, 32, sbase, 1, tid); CP_COMMIT();

    for (int t = 0; t < nt; ++t) {
        if (t + 2 < nt)
            issue_tile(A, B, K, N, bm, bn, (t + 2) * 32, sbase, (t + 2) % 3, tid);
        CP_COMMIT();
        CP_WAIT2();
        __syncthreads();

        const unsigned* Ab = smbuf + (t % 3) * AS_WORDS;
        const unsigned* Bb = smbuf + 3 * AS_WORDS + (t % 3) * BS_WORDS;

#pragma unroll
        for (int ks = 0; ks < 4; ++ks) {
            const int k0 = ks * 8;
            unsigned a[2][4];
#pragma unroll
            for (int m2 = 0; m2 < 2; ++m2) {
                const int mr = warpM * 32 + m2 * 16;
                a[m2][0] = Ab[(mr + g) * 36 + k0 + tig];
                a[m2][1] = Ab[(mr + g + 8) * 36 + k0 + tig];
                a[m2][2] = Ab[(mr + g) * 36 + k0 + tig + 4];
                a[m2][3] = Ab[(mr + g + 8) * 36 + k0 + tig + 4];
            }
#pragma unroll
            for (int j = 0; j < 8; ++j) {
                unsigned b[2];
                const unsigned nc = (unsigned)(warpN * 64 + j * 8 + g) ^ swz;
                b[0] = Bb[(k0 + tig) * 128 + nc];
                b[1] = Bb[(k0 + tig + 4) * 128 + nc];
                MMA_TF32(c[0][j], a[0], b);
                MMA_TF32(c[1][j], a[1], b);
            }
        }
        __syncthreads();
    }

#pragma unroll
    for (int m2 = 0; m2 < 2; ++m2) {
#pragma unroll
        for (int j = 0; j < 8; ++j) {
            const int row = bm + warpM * 32 + m2 * 16 + g;
            const int col = bn + warpN * 64 + j * 8 + 2 * tig;
            float2 v0 = make_float2(c[m2][j][0], c[m2][j][1]);
            float2 v1 = make_float2(c[m2][j][2], c[m2][j][3]);
            if (round_out) {
                v0.x = __uint_as_float(f2tf(v0.x));
                v0.y = __uint_as_float(f2tf(v0.y));
                v1.x = __uint_as_float(f2tf(v1.x));
                v1.y = __uint_as_float(f2tf(v1.y));
            }
            *(float2*)&C[(size_t)row * N + col]       = v0;
            *(float2*)&C[(size_t)(row + 8) * N + col] = v1;
        }
    }
}

__global__ __launch_bounds__(256, 2) void tgemm_ca(
    const float* __restrict__ A, const float* __restrict__ B,
    float* __restrict__ C, int N, int K)
{
    gemm_ca_body(A, B, C, N, K, false);
}

__global__ __launch_bounds__(256, 2) void tgemm_ca_qkv(
    const float* __restrict__ A, const float* __restrict__ W,
    float* __restrict__ C0, float* __restrict__ C1, float* __restrict__ C2)
{
    const int z = blockIdx.z;
    float* C = (z == 0) ? C0 : (z == 1) ? C1 : C2;
    gemm_ca_body(A, W + (size_t)z * C_ * C_, C, C_, C_, z < 2);  // round Q,K
}

// ============================================================================
// tf32 score row-max (R11 winner, unchanged)
// ============================================================================
__global__ __launch_bounds__(256, 2) void score_max_t(
    const float* __restrict__ Q, const float* __restrict__ K,
    float* __restrict__ m1)
{
    __shared__ unsigned Ks[2][64][68];
    __shared__ float buf[4][64];

    const int bh = blockIdx.y;
    const int b = bh >> 4, h = bh & 15;
    const int q0 = blockIdx.x * 64;
    const int tid = threadIdx.x;
    const int rowbase = (b * S_) * C_ + h * DH_;

    const int wid  = tid >> 5;
    const int lane = tid & 31;
    const int g    = lane >> 2;
    const int tig  = lane & 3;
    const int warpM = wid & 3;
    const int warpN = wid >> 2;

    const int ld_r = tid >> 2;
    const int ld_c = (tid & 3) * 16;

    {
        const float* qp = Q + rowbase + (q0 + ld_r) * C_ + ld_c;
#pragma unroll
        for (int j = 0; j < 4; ++j)
            *(uint4*)&Ks[0][ld_r][ld_c + j * 4] = *(const uint4*)(qp + j * 4);
    }
    __syncthreads();

    unsigned bq[4][8][2];
#pragma unroll
    for (int na = 0; na < 4; ++na) {
        const int nc = warpN * 32 + na * 8 + g;
#pragma unroll
        for (int ks = 0; ks < 8; ++ks) {
            bq[na][ks][0] = Ks[0][nc][ks * 8 + tig];
            bq[na][ks][1] = Ks[0][nc][ks * 8 + tig + 4];
        }
    }
    __syncthreads();

    float rmax[4][2];
#pragma unroll
    for (int na = 0; na < 4; ++na) { rmax[na][0] = -1e30f; rmax[na][1] = -1e30f; }

    uint4 kv[4];
    {
        const float* kp = K + rowbase + ld_r * C_ + ld_c;
#pragma unroll
        for (int j = 0; j < 4; ++j) kv[j] = *(const uint4*)(kp + j * 4);
    }

    for (int t = 0; t < S_ / 64; ++t) {
        const int cur = t & 1;
#pragma unroll
        for (int j = 0; j < 4; ++j)
            *(uint4*)&Ks[cur][ld_r][ld_c + j * 4] = kv[j];
        __syncthreads();

        if (t + 1 < S_ / 64) {
            const float* kp = K + rowbase + ((t + 1) * 64 + ld_r) * C_ + ld_c;
#pragma unroll
            for (int j = 0; j < 4; ++j) kv[j] = *(const uint4*)(kp + j * 4);
        }

        float c[4][4];
#pragma unroll
        for (int na = 0; na < 4; ++na)
#pragma unroll
            for (int r = 0; r < 4; ++r) c[na][r] = 0.f;

        const int mr = warpM * 16;
#pragma unroll
        for (int ks = 0; ks < 8; ++ks) {
            const int k0 = ks * 8;
            unsigned a[4];
            a[0] = Ks[cur][mr + g][k0 + tig];
            a[1] = Ks[cur][mr + g + 8][k0 + tig];
            a[2] = Ks[cur][mr + g][k0 + tig + 4];
            a[3] = Ks[cur][mr + g + 8][k0 + tig + 4];
#pragma unroll
            for (int na = 0; na < 4; ++na)
                MMA_TF32(c[na], a, bq[na][ks]);
        }

#pragma unroll
        for (int na = 0; na < 4; ++na) {
            rmax[na][0] = fmaxf(rmax[na][0], fmaxf(c[na][0], c[na][2]));
            rmax[na][1] = fmaxf(rmax[na][1], fmaxf(c[na][1], c[na][3]));
        }
    }

#pragma unroll
    for (int off = 4; off <= 16; off <<= 1)
#pragma unroll
        for (int na = 0; na < 4; ++na) {
            rmax[na][0] = fmaxf(rmax[na][0], __shfl_xor_sync(0xffffffffu, rmax[na][0], off));
            rmax[na][1] = fmaxf(rmax[na][1], __shfl_xor_sync(0xffffffffu, rmax[na][1], off));
        }

    if (g == 0) {
#pragma unroll
        for (int na = 0; na < 4; ++na) {
            buf[warpM][warpN * 32 + na * 8 + tig * 2 + 0] = rmax[na][0];
            buf[warpM][warpN * 32 + na * 8 + tig * 2 + 1] = rmax[na][1];
        }
    }
    __syncthreads();
    if (tid < 64) {
        float m = fmaxf(fmaxf(buf[0][tid], buf[1][tid]),
                        fmaxf(buf[2][tid], buf[3][tid]));
        m1[bh * S_ + q0 + tid] = m * 0.125f;
    }
}

// ============================================================================
// V column sums, two-stage (parallel over 8 key-chunks of 256)
// ============================================================================
__global__ __launch_bounds__(256) void vsum_part(
    const float* __restrict__ V, float* __restrict__ vsp)
{
    __shared__ float red[4][64];
    const int bh = blockIdx.x;
    const int ch = blockIdx.y;
    const int b = bh >> 4, h = bh & 15;
    const int tid = threadIdx.x;
    const int d = tid & 63, grp = tid >> 6;
    const float* p = V + (b * S_) * C_ + h * DH_ + d;
    float s = 0.f;
    for (int k = ch * 256 + grp; k < ch * 256 + 256; k += 4) s += p[k * C_];
    red[grp][d] = s;
    __syncthreads();
    if (tid < 64)
        vsp[(bh * 8 + ch) * 64 + tid] =
            red[0][tid] + red[1][tid] + red[2][tid] + red[3][tid];
}

__global__ __launch_bounds__(64) void vsum_fin(
    const float* __restrict__ vsp, float* __restrict__ vs)
{
    const int bh = blockIdx.x;
    const int tid = threadIdx.x;
    float s = 0.f;
#pragma unroll
    for (int ch = 0; ch < 8; ++ch) s += vsp[(bh * 8 + ch) * 64 + tid];
    vs[bh * 64 + tid] = s;
}

// ============================================================================
// Tensor-core banded attention, 64-key tiles (15 syncs vs 30).
// GEMM1 reuses score_max's warp layout: warpM=wid&3 (4x16 keys),
// warpN=wid>>2 (2x32 queries), bq[4][8][2] hoisted.
// GEMM2: m=64q (warpM rows of 16), n=64d (warpN cols of 32).
// smem words: Qs 64*68 | Ks 64*68 | Vs 64*68 | Ws 64*76 | zred 4*64
// ============================================================================
#define BD_QS 0
#define BD_KS 4352
#define BD_VS 8704
#define BD_WS 13056
#define BD_ZR 17920
#define BAND_SMEM_BYTES (18176 * 4)

__global__ __launch_bounds__(256, 2) void band_attn_t(
    const float* __restrict__ Q, const float* __restrict__ K,
    const float* __restrict__ V, const float* __restrict__ m1,
    const float* __restrict__ vs, float* __restrict__ O)
{
    extern __shared__ unsigned bsm[];
    unsigned* Qs = bsm + BD_QS;
    unsigned* Ks = bsm + BD_KS;
    unsigned* Vs = bsm + BD_VS;
    unsigned* Ws = bsm + BD_WS;
    float* zred  = (float*)(bsm + BD_ZR);

    const int bh = blockIdx.y;
    const int b = bh >> 4, h = bh & 15;
    const int q0 = blockIdx.x * 64;
    const int tid = threadIdx.x;
    const int rowbase = (b * S_) * C_ + h * DH_;

    const int wid  = tid >> 5;
    const int lane = tid & 31;
    const int g    = lane >> 2;
    const int tig  = lane & 3;
    const int warpM = wid & 3;     // GEMM1: key rows / GEMM2: q rows
    const int warpN = wid >> 2;    // GEMM1: q cols / GEMM2: d cols

    const int ld_r = tid >> 2;           // 0..63
    const int ld_c = (tid & 3) * 16;

    // load Q tile (pre-rounded, plain copy)
    {
        const float* qp = Q + rowbase + (q0 + ld_r) * C_ + ld_c;
#pragma unroll
        for (int j = 0; j < 4; ++j)
            *(uint4*)&Qs[ld_r * 68 + ld_c + j * 4] = *(const uint4*)(qp + j * 4);
    }
    __syncthreads();

    unsigned bq[4][8][2];
#pragma unroll
    for (int na = 0; na < 4; ++na) {
        const int nc = warpN * 32 + na * 8 + g;
#pragma unroll
        for (int ks = 0; ks < 8; ++ks) {
            bq[na][ks][0] = Qs[nc * 68 + ks * 8 + tig];
            bq[na][ks][1] = Qs[nc * 68 + ks * 8 + tig + 4];
        }
    }
    float m1c[4][2];
#pragma unroll
    for (int na = 0; na < 4; ++na) {
        const int qc = q0 + warpN * 32 + na * 8 + 2 * tig;
        m1c[na][0] = m1[bh * S_ + qc];
        m1c[na][1] = m1[bh * S_ + qc + 1];
    }

    float o[4][4];
#pragma unroll
    for (int na = 0; na < 4; ++na)
#pragma unroll
        for (int r = 0; r < 4; ++r) o[na][r] = 0.f;
    float zp[4][2];
#pragma unroll
    for (int na = 0; na < 4; ++na) { zp[na][0] = 0.f; zp[na][1] = 0.f; }

    const int klo  = (q0 >= 128) ? q0 - 128 : 0;             // 64-aligned
    const int kend = (q0 + 192 < S_) ? q0 + 192 : S_;

    for (int kt = klo; kt < kend; kt += 64) {
        __syncthreads();   // prev GEMM2 done; tiles safe to overwrite
        // load K (plain copy) / V (round) tiles: 64 rows x 64 d
        {
            const float* kp = K + rowbase + (kt + ld_r) * C_ + ld_c;
            const float* vp = V + rowbase + (kt + ld_r) * C_ + ld_c;
#pragma unroll
            for (int j = 0; j < 4; ++j) {
                *(uint4*)&Ks[ld_r * 68 + ld_c + j * 4] = *(const uint4*)(kp + j * 4);
                float4 c = *(const float4*)(vp + j * 4);
                uint4 tc;
                tc.x = f2tf(c.x); tc.y = f2tf(c.y); tc.z = f2tf(c.z); tc.w = f2tf(c.w);
                *(uint4*)&Vs[ld_r * 68 + ld_c + j * 4] = tc;
            }
        }
        __syncthreads();

        // ---- GEMM1: S^T[64key][64q] = K @ Q^T ----
        float c[4][4];
#pragma unroll
        for (int na = 0; na < 4; ++na)
#pragma unroll
            for (int r = 0; r < 4; ++r) c[na][r] = 0.f;

        const int mr = warpM * 16;
#pragma unroll
        for (int ks = 0; ks < 8; ++ks) {
            const int k0 = ks * 8;
            unsigned a[4];
            a[0] = Ks[(mr + g) * 68 + k0 + tig];
            a[1] = Ks[(mr + g + 8) * 68 + k0 + tig];
            a[2] = Ks[(mr + g) * 68 + k0 + tig + 4];
            a[3] = Ks[(mr + g + 8) * 68 + k0 + tig + 4];
#pragma unroll
            for (int na = 0; na < 4; ++na)
                MMA_TF32(c[na], a, bq[na][ks]);
        }

        // ---- exp / band mask / Z -> W^T ----
#pragma unroll
        for (int na = 0; na < 4; ++na) {
            const int colq = warpN * 32 + na * 8 + 2 * tig;
#pragma unroll
            for (int r2 = 0; r2 < 2; ++r2) {
                const int keyrow = warpM * 16 + g + r2 * 8;
                const int key = kt + keyrow;
#pragma unroll
                for (int j = 0; j < 2; ++j) {
                    const float sv = c[na][r2 * 2 + j];
                    const int d = key - (q0 + colq + j);
                    float tt = __expf(sv * 0.125f - m1c[na][j]);
                    float w = __expf(tt) - 1.0f;
                    if (d < -128 || d > 127) w = 0.f;
                    const unsigned wt = f2tf(w);
                    zp[na][j] += __uint_as_float(wt);
                    Ws[keyrow * 76 + colq + j] = wt;
                }
            }
        }
        __syncthreads();   // W^T visible

        // ---- GEMM2: O[64q][64d] += W @ V ----
        const int mr2 = warpM * 16;
#pragma unroll
        for (int ks = 0; ks < 8; ++ks) {
            const int k0 = ks * 8;
            unsigned a[4];
            a[0] = Ws[(k0 + tig) * 76 + mr2 + g];
            a[1] = Ws[(k0 + tig) * 76 + mr2 + g + 8];
            a[2] = Ws[(k0 + tig + 4) * 76 + mr2 + g];
            a[3] = Ws[(k0 + tig + 4) * 76 + mr2 + g + 8];
#pragma unroll
            for (int na = 0; na < 4; ++na) {
                unsigned bb[2];
                const int nc = warpN * 32 + na * 8 + g;
                bb[0] = Vs[(k0 + tig) * 68 + nc];
                bb[1] = Vs[(k0 + tig + 4) * 68 + nc];
                MMA_TF32(o[na], a, bb);
            }
        }
    }

    // ---- Z reduction: over g lanes, then over 4 key-warp rows ----
#pragma unroll
    for (int off = 4; off <= 16; off <<= 1)
#pragma unroll
        for (int na = 0; na < 4; ++na) {
            zp[na][0] += __shfl_xor_sync(0xffffffffu, zp[na][0], off);
            zp[na][1] += __shfl_xor_sync(0xffffffffu, zp[na][1], off);
        }
    if (g == 0) {
#pragma unroll
        for (int na = 0; na < 4; ++na) {
            zred[warpM * 64 + warpN * 32 + na * 8 + 2 * tig + 0] = zp[na][0];
            zred[warpM * 64 + warpN * 32 + na * 8 + 2 * tig + 1] = zp[na][1];
        }
    }
    __syncthreads();

    // ---- epilogue: out = (O + vsum) / (S + Z), tf32-rounded ----
    const float* vsp = vs + bh * 64;
#pragma unroll
    for (int r2 = 0; r2 < 2; ++r2) {
        const int row = warpM * 16 + g + r2 * 8;      // query within tile
        const float inv = 1.0f / ((float)S_ + zred[row] + zred[64 + row] +
                                  zred[128 + row] + zred[192 + row]);
        float* op = O + rowbase + (q0 + row) * C_;
#pragma unroll
        for (int na = 0; na < 4; ++na) {
            const int col = warpN * 32 + na * 8 + 2 * tig;
            float2 ov;
            ov.x = __uint_as_float(f2tf((o[na][r2 * 2 + 0] + vsp[col])     * inv));
            ov.y = __uint_as_float(f2tf((o[na][r2 * 2 + 1] + vsp[col + 1]) * inv));
            *(float2*)(op + col) = ov;
        }
    }
}

// ============================================================================
extern "C" void kernel_launch(void* const* d_in, const int* in_sizes, int n_in,
                              void* d_out, int out_size)
{
    (void)in_sizes; (void)n_in; (void)out_size;
    const float* x  = (const float*)d_in[0];
    const float* Wq = (const float*)d_in[1];
    const float* Wk = (const float*)d_in[2];
    const float* Wv = (const float*)d_in[3];
    const float* Wo = (const float*)d_in[4];
    float* out = (float*)d_out;

    float *Qp, *Kp, *Vp, *Ap, *Xp, *Wtp, *m1p, *vsp, *vspp;
    cudaGetSymbolAddress((void**)&Qp,  g_Q);
    cudaGetSymbolAddress((void**)&Kp,  g_K);
    cudaGetSymbolAddress((void**)&Vp,  g_V);
    cudaGetSymbolAddress((void**)&Ap,  g_A);
    cudaGetSymbolAddress((void**)&Xp,  g_X);
    cudaGetSymbolAddress((void**)&Wtp, g_Wt);
    cudaGetSymbolAddress((void**)&m1p, g_m1);
    cudaGetSymbolAddress((void**)&vsp, g_vs);
    cudaGetSymbolAddress((void**)&vspp, g_vsp);

    cudaFuncSetAttribute(tgemm_ca,
                         cudaFuncAttributeMaxDynamicSharedMemorySize,
                         GEMM_SMEM_BYTES);
    cudaFuncSetAttribute(tgemm_ca_qkv,
                         cudaFuncAttributeMaxDynamicSharedMemorySize,
                         GEMM_SMEM_BYTES);
    cudaFuncSetAttribute(band_attn_t,
                         cudaFuncAttributeMaxDynamicSharedMemorySize,
                         BAND_SMEM_BYTES);

    round_all<<<(2 * 1024 * 1024) / 256, 256>>>(x, Wq, Wk, Wv, Wo, Xp, Wtp);

    dim3 gq(C_ / 128, M_ / 128, 3);         // (8, 32, 3)
    tgemm_ca_qkv<<<gq, 256, GEMM_SMEM_BYTES>>>(Xp, Wtp, Qp, Kp, Vp);

    score_max_t<<<dim3(S_ / 64, B_ * H_), 256>>>(Qp, Kp, m1p);
    vsum_part<<<dim3(B_ * H_, 8), 256>>>(Vp, vspp);
    vsum_fin<<<B_ * H_, 64>>>(vspp, vsp);
    band_attn_t<<<dim3(S_ / 64, B_ * H_), 256, BAND_SMEM_BYTES>>>(
        Qp, Kp, Vp, m1p, vsp, Ap);

    dim3 gg(C_ / 128, M_ / 128);            // (8, 32)
    tgemm_ca<<<gg, 256, GEMM_SMEM_BYTES>>>(Ap, Wtp + 3 * C_ * C_, out, C_, C_);
}

// round 13
// speedup vs baseline: 1.0194x; 1.0194x over previous
#include <cuda_runtime.h>
#include <math.h>
#include <cstdint>

#define B_   2
#define S_   2048
#define C_   1024
#define H_   16
#define DH_  64
#define M_   (B_ * S_)       // 4096 rows

// ---- scratch (device globals; no allocation allowed) ----
__device__ float g_Q[M_ * C_];           // tf32-rounded (GEMM epilogue)
__device__ float g_K[M_ * C_];           // tf32-rounded (GEMM epilogue)
__device__ float g_V[M_ * C_];           // exact fp32
__device__ float g_A[M_ * C_];           // attention output (tf32-rounded)
__device__ float g_X[M_ * C_];           // tf32-rounded x
__device__ float g_Wt[4 * C_ * C_];      // tf32-rounded weights
__device__ float g_m1[B_ * H_ * S_];     // full-row max of scores (already /8)
__device__ float g_vs[B_ * H_ * DH_];    // sum over all keys of V per (b,h)
__device__ float g_vsp[B_ * H_ * 8 * DH_]; // vsum partials

__device__ __forceinline__ unsigned f2tf(float x) {
    unsigned r;
    asm("cvt.rna.tf32.f32 %0, %1;" : "=r"(r) : "f"(x));
    return r;
}

__device__ __forceinline__ uint32_t s2u(const void* p) {
    uint32_t a;
    asm("{ .reg .u64 t; cvta.to.shared.u64 t, %1; cvt.u32.u64 %0, t; }"
        : "=r"(a) : "l"(p));
    return a;
}

__device__ __forceinline__ void cp16(uint32_t d, const void* s) {
    asm volatile("cp.async.cg.shared.global [%0], [%1], 16;" :: "r"(d), "l"(s));
}
#define CP_COMMIT() asm volatile("cp.async.commit_group;" ::: "memory")
#define CP_WAIT2()  asm volatile("cp.async.wait_group 2;" ::: "memory")

#define MMA_TF32(c, a, b)                                                     \
    asm volatile(                                                             \
        "mma.sync.aligned.m16n8k8.row.col.f32.tf32.tf32.f32 "                 \
        "{%0,%1,%2,%3},{%4,%5,%6,%7},{%8,%9},{%0,%1,%2,%3};"                  \
        : "+f"((c)[0]), "+f"((c)[1]), "+f"((c)[2]), "+f"((c)[3])              \
        : "r"((a)[0]), "r"((a)[1]), "r"((a)[2]), "r"((a)[3]),                 \
          "r"((b)[0]), "r"((b)[1]))

// ============================================================================
// Fused tf32 rounding: x (1M float4) then Wq,Wk,Wv,Wo (256K float4 each).
// ============================================================================
__global__ __launch_bounds__(256) void round_all(
    const float* __restrict__ x,
    const float* __restrict__ W0, const float* __restrict__ W1,
    const float* __restrict__ W2, const float* __restrict__ W3,
    float* __restrict__ X, float* __restrict__ Wt)
{
    const int i = blockIdx.x * 256 + threadIdx.x;   // 0 .. 2M-1 float4
    if (i < (M_ * C_ / 4)) {
        float4 v = ((const float4*)x)[i];
        uint4 t;
        t.x = f2tf(v.x); t.y = f2tf(v.y); t.z = f2tf(v.z); t.w = f2tf(v.w);
        ((uint4*)X)[i] = t;
    } else {
        const int w = i - (M_ * C_ / 4);
        const int z = w >> 18;
        const int j = w & ((1 << 18) - 1);
        const float* src = (z == 0) ? W0 : (z == 1) ? W1 : (z == 2) ? W2 : W3;
        float* dst = Wt + (size_t)z * C_ * C_;
        float4 v = ((const float4*)src)[j];
        uint4 t;
        t.x = f2tf(v.x); t.y = f2tf(v.y); t.z = f2tf(v.z); t.w = f2tf(v.w);
        ((uint4*)dst)[j] = t;
    }
}

// ============================================================================
// cp.async 3-stage tf32 GEMM (R9 winner) + optional tf32-rounded epilogue
// ============================================================================
#define AS_WORDS (128 * 36)
#define BS_WORDS (32 * 128)
#define GEMM_SMEM_BYTES (3 * (AS_WORDS + BS_WORDS) * 4)

__device__ __forceinline__ void issue_tile(
    const float* __restrict__ A, const float* __restrict__ B,
    int K, int N, int bm, int bn, int kb,
    uint32_t sbase, int stage, int tid)
{
#pragma unroll
    for (int u = 0; u < 4; ++u) {
        const int f = tid + 256 * u;
        const int row = f >> 3;
        const int k4 = (f & 7) * 4;
        cp16(sbase + (uint32_t)(stage * AS_WORDS + row * 36 + k4) * 4,
             A + (size_t)(bm + row) * K + kb + k4);
    }
    const int bk = tid >> 3;
    const int n0 = (tid & 7) * 16;
    const unsigned sw = (bk & 3) << 3;
#pragma unroll
    for (int j = 0; j < 4; ++j) {
        cp16(sbase + (uint32_t)(3 * AS_WORDS + stage * BS_WORDS + bk * 128 +
                                ((n0 + j * 4) ^ sw)) * 4,
             B + (size_t)(kb + bk) * N + bn + n0 + j * 4);
    }
}

__device__ __forceinline__ void gemm_ca_body(
    const float* __restrict__ A, const float* __restrict__ B,
    float* __restrict__ C, int N, int K, bool round_out)
{
    extern __shared__ unsigned smbuf[];
    const uint32_t sbase = s2u(smbuf);

    const int tid = threadIdx.x;
    const int bm = blockIdx.y * 128;
    const int bn = blockIdx.x * 128;

    const int wid  = tid >> 5;
    const int lane = tid & 31;
    const int g    = lane >> 2;
    const int tig  = lane & 3;
    const int warpM = wid >> 1;
    const int warpN = wid & 1;
    const unsigned swz = tig << 3;

    float c[2][8][4];
#pragma unroll
    for (int i = 0; i < 2; ++i)
#pragma unroll
        for (int j = 0; j < 8; ++j)
#pragma unroll
            for (int r = 0; r < 4; ++r) c[i][j][r] = 0.f;

    const int nt = K >> 5;

    issue_tile(A, B, K, N, bm, bn, 0,  sbase, 0, tid); CP_COMMIT();
    issue_tile(A, B, K, N, bm, bn, 32, sbase, 1, tid); CP_COMMIT();

    for (int t = 0; t < nt; ++t) {
        if (t + 2 < nt)
            issue_tile(A, B, K, N, bm, bn, (t + 2) * 32, sbase, (t + 2) % 3, tid);
        CP_COMMIT();
        CP_WAIT2();
        __syncthreads();

        const unsigned* Ab = smbuf + (t % 3) * AS_WORDS;
        const unsigned* Bb = smbuf + 3 * AS_WORDS + (t % 3) * BS_WORDS;

#pragma unroll
        for (int ks = 0; ks < 4; ++ks) {
            const int k0 = ks * 8;
            unsigned a[2][4];
#pragma unroll
            for (int m2 = 0; m2 < 2; ++m2) {
                const int mr = warpM * 32 + m2 * 16;
                a[m2][0] = Ab[(mr + g) * 36 + k0 + tig];
                a[m2][1] = Ab[(mr + g + 8) * 36 + k0 + tig];
                a[m2][2] = Ab[(mr + g) * 36 + k0 + tig + 4];
                a[m2][3] = Ab[(mr + g + 8) * 36 + k0 + tig + 4];
            }
#pragma unroll
            for (int j = 0; j < 8; ++j) {
                unsigned b[2];
                const unsigned nc = (unsigned)(warpN * 64 + j * 8 + g) ^ swz;
                b[0] = Bb[(k0 + tig) * 128 + nc];
                b[1] = Bb[(k0 + tig + 4) * 128 + nc];
                MMA_TF32(c[0][j], a[0], b);
                MMA_TF32(c[1][j], a[1], b);
            }
        }
        __syncthreads();
    }

#pragma unroll
    for (int m2 = 0; m2 < 2; ++m2) {
#pragma unroll
        for (int j = 0; j < 8; ++j) {
            const int row = bm + warpM * 32 + m2 * 16 + g;
            const int col = bn + warpN * 64 + j * 8 + 2 * tig;
            float2 v0 = make_float2(c[m2][j][0], c[m2][j][1]);
            float2 v1 = make_float2(c[m2][j][2], c[m2][j][3]);
            if (round_out) {
                v0.x = __uint_as_float(f2tf(v0.x));
                v0.y = __uint_as_float(f2tf(v0.y));
                v1.x = __uint_as_float(f2tf(v1.x));
                v1.y = __uint_as_float(f2tf(v1.y));
            }
            *(float2*)&C[(size_t)row * N + col]       = v0;
            *(float2*)&C[(size_t)(row + 8) * N + col] = v1;
        }
    }
}

__global__ __launch_bounds__(256, 2) void tgemm_ca(
    const float* __restrict__ A, const float* __restrict__ B,
    float* __restrict__ C, int N, int K)
{
    gemm_ca_body(A, B, C, N, K, false);
}

__global__ __launch_bounds__(256, 2) void tgemm_ca_qkv(
    const float* __restrict__ A, const float* __restrict__ W,
    float* __restrict__ C0, float* __restrict__ C1, float* __restrict__ C2)
{
    const int z = blockIdx.z;
    float* C = (z == 0) ? C0 : (z == 1) ? C1 : C2;
    gemm_ca_body(A, W + (size_t)z * C_ * C_, C, C_, C_, z < 2);  // round Q,K
}

// ============================================================================
// tf32 score row-max (R11 winner, unchanged)
// ============================================================================
__global__ __launch_bounds__(256, 2) void score_max_t(
    const float* __restrict__ Q, const float* __restrict__ K,
    float* __restrict__ m1)
{
    __shared__ unsigned Ks[2][64][68];
    __shared__ float buf[4][64];

    const int bh = blockIdx.y;
    const int b = bh >> 4, h = bh & 15;
    const int q0 = blockIdx.x * 64;
    const int tid = threadIdx.x;
    const int rowbase = (b * S_) * C_ + h * DH_;

    const int wid  = tid >> 5;
    const int lane = tid & 31;
    const int g    = lane >> 2;
    const int tig  = lane & 3;
    const int warpM = wid & 3;
    const int warpN = wid >> 2;

    const int ld_r = tid >> 2;
    const int ld_c = (tid & 3) * 16;

    {
        const float* qp = Q + rowbase + (q0 + ld_r) * C_ + ld_c;
#pragma unroll
        for (int j = 0; j < 4; ++j)
            *(uint4*)&Ks[0][ld_r][ld_c + j * 4] = *(const uint4*)(qp + j * 4);
    }
    __syncthreads();

    unsigned bq[4][8][2];
#pragma unroll
    for (int na = 0; na < 4; ++na) {
        const int nc = warpN * 32 + na * 8 + g;
#pragma unroll
        for (int ks = 0; ks < 8; ++ks) {
            bq[na][ks][0] = Ks[0][nc][ks * 8 + tig];
            bq[na][ks][1] = Ks[0][nc][ks * 8 + tig + 4];
        }
    }
    __syncthreads();

    float rmax[4][2];
#pragma unroll
    for (int na = 0; na < 4; ++na) { rmax[na][0] = -1e30f; rmax[na][1] = -1e30f; }

    uint4 kv[4];
    {
        const float* kp = K + rowbase + ld_r * C_ + ld_c;
#pragma unroll
        for (int j = 0; j < 4; ++j) kv[j] = *(const uint4*)(kp + j * 4);
    }

    for (int t = 0; t < S_ / 64; ++t) {
        const int cur = t & 1;
#pragma unroll
        for (int j = 0; j < 4; ++j)
            *(uint4*)&Ks[cur][ld_r][ld_c + j * 4] = kv[j];
        __syncthreads();

        if (t + 1 < S_ / 64) {
            const float* kp = K + rowbase + ((t + 1) * 64 + ld_r) * C_ + ld_c;
#pragma unroll
            for (int j = 0; j < 4; ++j) kv[j] = *(const uint4*)(kp + j * 4);
        }

        float c[4][4];
#pragma unroll
        for (int na = 0; na < 4; ++na)
#pragma unroll
            for (int r = 0; r < 4; ++r) c[na][r] = 0.f;

        const int mr = warpM * 16;
#pragma unroll
        for (int ks = 0; ks < 8; ++ks) {
            const int k0 = ks * 8;
            unsigned a[4];
            a[0] = Ks[cur][mr + g][k0 + tig];
            a[1] = Ks[cur][mr + g + 8][k0 + tig];
            a[2] = Ks[cur][mr + g][k0 + tig + 4];
            a[3] = Ks[cur][mr + g + 8][k0 + tig + 4];
#pragma unroll
            for (int na = 0; na < 4; ++na)
                MMA_TF32(c[na], a, bq[na][ks]);
        }

#pragma unroll
        for (int na = 0; na < 4; ++na) {
            rmax[na][0] = fmaxf(rmax[na][0], fmaxf(c[na][0], c[na][2]));
            rmax[na][1] = fmaxf(rmax[na][1], fmaxf(c[na][1], c[na][3]));
        }
    }

#pragma unroll
    for (int off = 4; off <= 16; off <<= 1)
#pragma unroll
        for (int na = 0; na < 4; ++na) {
            rmax[na][0] = fmaxf(rmax[na][0], __shfl_xor_sync(0xffffffffu, rmax[na][0], off));
            rmax[na][1] = fmaxf(rmax[na][1], __shfl_xor_sync(0xffffffffu, rmax[na][1], off));
        }

    if (g == 0) {
#pragma unroll
        for (int na = 0; na < 4; ++na) {
            buf[warpM][warpN * 32 + na * 8 + tig * 2 + 0] = rmax[na][0];
            buf[warpM][warpN * 32 + na * 8 + tig * 2 + 1] = rmax[na][1];
        }
    }
    __syncthreads();
    if (tid < 64) {
        float m = fmaxf(fmaxf(buf[0][tid], buf[1][tid]),
                        fmaxf(buf[2][tid], buf[3][tid]));
        m1[bh * S_ + q0 + tid] = m * 0.125f;
    }
}

// ============================================================================
// V column sums, two-stage (parallel over 8 key-chunks of 256) — R12 winner
// ============================================================================
__global__ __launch_bounds__(256) void vsum_part(
    const float* __restrict__ V, float* __restrict__ vsp)
{
    __shared__ float red[4][64];
    const int bh = blockIdx.x;
    const int ch = blockIdx.y;
    const int b = bh >> 4, h = bh & 15;
    const int tid = threadIdx.x;
    const int d = tid & 63, grp = tid >> 6;
    const float* p = V + (b * S_) * C_ + h * DH_ + d;
    float s = 0.f;
    for (int k = ch * 256 + grp; k < ch * 256 + 256; k += 4) s += p[k * C_];
    red[grp][d] = s;
    __syncthreads();
    if (tid < 64)
        vsp[(bh * 8 + ch) * 64 + tid] =
            red[0][tid] + red[1][tid] + red[2][tid] + red[3][tid];
}

__global__ __launch_bounds__(64) void vsum_fin(
    const float* __restrict__ vsp, float* __restrict__ vs)
{
    const int bh = blockIdx.x;
    const int tid = threadIdx.x;
    float s = 0.f;
#pragma unroll
    for (int ch = 0; ch < 8; ++ch) s += vsp[(bh * 8 + ch) * 64 + tid];
    vs[bh * 64 + tid] = s;
}

// ============================================================================
// Tensor-core banded attention (R11 winner: static smem, 32-key tiles)
// ============================================================================
__global__ __launch_bounds__(256) void band_attn_t(
    const float* __restrict__ Q, const float* __restrict__ K,
    const float* __restrict__ V, const float* __restrict__ m1,
    const float* __restrict__ vs, float* __restrict__ O)
{
    __shared__ unsigned Qs[64][68];
    __shared__ unsigned Ks[32][76];
    __shared__ unsigned Vs[32][76];
    __shared__ unsigned Ws[32][76];
    __shared__ float zred[2][64];

    const int bh = blockIdx.y;
    const int b = bh >> 4, h = bh & 15;
    const int q0 = blockIdx.x * 64;
    const int tid = threadIdx.x;
    const int rowbase = (b * S_) * C_ + h * DH_;

    const int wid  = tid >> 5;
    const int lane = tid & 31;
    const int g    = lane >> 2;
    const int tig  = lane & 3;
    const int wm1 = wid & 1;
    const int wn1 = wid >> 1;
    const int wm2 = wid >> 1;
    const int wn2 = wid & 1;

    {
        const int r  = tid >> 2;
        const int c0 = (tid & 3) * 16;
        const float* qp = Q + rowbase + (q0 + r) * C_ + c0;
#pragma unroll
        for (int j = 0; j < 4; ++j)
            *(uint4*)&Qs[r][c0 + j * 4] = *(const uint4*)(qp + j * 4);
    }
    __syncthreads();

    unsigned bq[2][8][2];
#pragma unroll
    for (int na = 0; na < 2; ++na) {
        const int nc = wn1 * 16 + na * 8 + g;
#pragma unroll
        for (int ks = 0; ks < 8; ++ks) {
            bq[na][ks][0] = Qs[nc][ks * 8 + tig];
            bq[na][ks][1] = Qs[nc][ks * 8 + tig + 4];
        }
    }
    float m1c[2][2];
#pragma unroll
    for (int na = 0; na < 2; ++na) {
        const int qc = q0 + wn1 * 16 + na * 8 + 2 * tig;
        m1c[na][0] = m1[bh * S_ + qc];
        m1c[na][1] = m1[bh * S_ + qc + 1];
    }

    float o[4][4];
#pragma unroll
    for (int na = 0; na < 4; ++na)
#pragma unroll
        for (int r = 0; r < 4; ++r) o[na][r] = 0.f;
    float zp[2][2] = {{0.f, 0.f}, {0.f, 0.f}};

    const int klo  = (q0 >= 128) ? q0 - 128 : 0;
    const int kend = (q0 + 192 < S_) ? q0 + 192 : S_;

    for (int kt = klo; kt < kend; kt += 32) {
        __syncthreads();
        {
            const int r  = tid >> 3;
            const int c0 = (tid & 7) * 8;
            const float* kp = K + rowbase + (kt + r) * C_ + c0;
            const float* vp = V + rowbase + (kt + r) * C_ + c0;
#pragma unroll
            for (int j = 0; j < 2; ++j) {
                *(uint4*)&Ks[r][c0 + j * 4] = *(const uint4*)(kp + j * 4);
                float4 c = *(const float4*)(vp + j * 4);
                uint4 tc;
                tc.x = f2tf(c.x); tc.y = f2tf(c.y); tc.z = f2tf(c.z); tc.w = f2tf(c.w);
                *(uint4*)&Vs[r][c0 + j * 4] = tc;
            }
        }
        __syncthreads();

        float s[2][4];
#pragma unroll
        for (int na = 0; na < 2; ++na)
#pragma unroll
            for (int r = 0; r < 4; ++r) s[na][r] = 0.f;

        const int mr1 = wm1 * 16;
#pragma unroll
        for (int ks = 0; ks < 8; ++ks) {
            const int k0 = ks * 8;
            unsigned a[4];
            a[0] = Ks[mr1 + g][k0 + tig];
            a[1] = Ks[mr1 + g + 8][k0 + tig];
            a[2] = Ks[mr1 + g][k0 + tig + 4];
            a[3] = Ks[mr1 + g + 8][k0 + tig + 4];
            MMA_TF32(s[0], a, bq[0][ks]);
            MMA_TF32(s[1], a, bq[1][ks]);
        }

#pragma unroll
        for (int na = 0; na < 2; ++na) {
            const int colq = wn1 * 16 + na * 8 + 2 * tig;
#pragma unroll
            for (int r2 = 0; r2 < 2; ++r2) {
                const int keyrow = wm1 * 16 + g + r2 * 8;
                const int key = kt + keyrow;
#pragma unroll
                for (int j = 0; j < 2; ++j) {
                    const float sv = s[na][r2 * 2 + j];
                    const int d = key - (q0 + colq + j);
                    float tt = __expf(sv * 0.125f - m1c[na][j]);
                    float w = __expf(tt) - 1.0f;
                    if (d < -128 || d > 127) w = 0.f;
                    const unsigned wt = f2tf(w);
                    zp[na][j] += __uint_as_float(wt);
                    Ws[keyrow][colq + j] = wt;
                }
            }
        }
        __syncthreads();

        const int mr2 = wm2 * 16;
#pragma unroll
        for (int ks = 0; ks < 4; ++ks) {
            const int k0 = ks * 8;
            unsigned a[4];
            a[0] = Ws[k0 + tig][mr2 + g];
            a[1] = Ws[k0 + tig][mr2 + g + 8];
            a[2] = Ws[k0 + tig + 4][mr2 + g];
            a[3] = Ws[k0 + tig + 4][mr2 + g + 8];
#pragma unroll
            for (int na = 0; na < 4; ++na) {
                unsigned bb[2];
                const int nc = wn2 * 32 + na * 8 + g;
                bb[0] = Vs[k0 + tig][nc];
                bb[1] = Vs[k0 + tig + 4][nc];
                MMA_TF32(o[na], a, bb);
            }
        }
    }

#pragma unroll
    for (int off = 4; off <= 16; off <<= 1)
#pragma unroll
        for (int na = 0; na < 2; ++na) {
            zp[na][0] += __shfl_xor_sync(0xffffffffu, zp[na][0], off);
            zp[na][1] += __shfl_xor_sync(0xffffffffu, zp[na][1], off);
        }
    if (g == 0) {
#pragma unroll
        for (int na = 0; na < 2; ++na) {
            zred[wm1][wn1 * 16 + na * 8 + 2 * tig + 0] = zp[na][0];
            zred[wm1][wn1 * 16 + na * 8 + 2 * tig + 1] = zp[na][1];
        }
    }
    __syncthreads();

    const float* vsp = vs + bh * 64;
#pragma unroll
    for (int r2 = 0; r2 < 2; ++r2) {
        const int row = wm2 * 16 + g + r2 * 8;
        const float inv = 1.0f / ((float)S_ + zred[0][row] + zred[1][row]);
        float* op = O + rowbase + (q0 + row) * C_;
#pragma unroll
        for (int na = 0; na < 4; ++na) {
            const int col = wn2 * 32 + na * 8 + 2 * tig;
            float2 ov;
            ov.x = __uint_as_float(f2tf((o[na][r2 * 2 + 0] + vsp[col])     * inv));
            ov.y = __uint_as_float(f2tf((o[na][r2 * 2 + 1] + vsp[col + 1]) * inv));
            *(float2*)(op + col) = ov;
        }
    }
}

// ============================================================================
extern "C" void kernel_launch(void* const* d_in, const int* in_sizes, int n_in,
                              void* d_out, int out_size)
{
    (void)in_sizes; (void)n_in; (void)out_size;
    const float* x  = (const float*)d_in[0];
    const float* Wq = (const float*)d_in[1];
    const float* Wk = (const float*)d_in[2];
    const float* Wv = (const float*)d_in[3];
    const float* Wo = (const float*)d_in[4];
    float* out = (float*)d_out;

    float *Qp, *Kp, *Vp, *Ap, *Xp, *Wtp, *m1p, *vsp, *vspp;
    cudaGetSymbolAddress((void**)&Qp,  g_Q);
    cudaGetSymbolAddress((void**)&Kp,  g_K);
    cudaGetSymbolAddress((void**)&Vp,  g_V);
    cudaGetSymbolAddress((void**)&Ap,  g_A);
    cudaGetSymbolAddress((void**)&Xp,  g_X);
    cudaGetSymbolAddress((void**)&Wtp, g_Wt);
    cudaGetSymbolAddress((void**)&m1p, g_m1);
    cudaGetSymbolAddress((void**)&vsp, g_vs);
    cudaGetSymbolAddress((void**)&vspp, g_vsp);

    cudaFuncSetAttribute(tgemm_ca,
                         cudaFuncAttributeMaxDynamicSharedMemorySize,
                         GEMM_SMEM_BYTES);
    cudaFuncSetAttribute(tgemm_ca_qkv,
                         cudaFuncAttributeMaxDynamicSharedMemorySize,
                         GEMM_SMEM_BYTES);

    round_all<<<(2 * 1024 * 1024) / 256, 256>>>(x, Wq, Wk, Wv, Wo, Xp, Wtp);

    dim3 gq(C_ / 128, M_ / 128, 3);         // (8, 32, 3)
    tgemm_ca_qkv<<<gq, 256, GEMM_SMEM_BYTES>>>(Xp, Wtp, Qp, Kp, Vp);

    score_max_t<<<dim3(S_ / 64, B_ * H_), 256>>>(Qp, Kp, m1p);
    vsum_part<<<dim3(B_ * H_, 8), 256>>>(Vp, vspp);
    vsum_fin<<<B_ * H_, 64>>>(vspp, vsp);
    band_attn_t<<<dim3(S_ / 64, B_ * H_), 256>>>(Qp, Kp, Vp, m1p, vsp, Ap);

    dim3 gg(C_ / 128, M_ / 128);            // (8, 32)
    tgemm_ca<<<gg, 256, GEMM_SMEM_BYTES>>>(Ap, Wtp + 3 * C_ * C_, out, C_, C_);
}

// round 14
// speedup vs baseline: 1.7923x; 1.7581x over previous
#include <cuda_runtime.h>
#include <cuda_fp16.h>
#include <math.h>
#include <cstdint>

#define B_   2
#define S_   2048
#define C_   1024
#define H_   16
#define DH_  64
#define M_   (B_ * S_)       // 4096 rows

// ---- scratch (device globals; no allocation allowed) ----
__device__ __half g_Qh[M_ * C_];         // fp16 Q (GEMM epilogue)
__device__ __half g_Kh[M_ * C_];         // fp16 K
__device__ float  g_V [M_ * C_];         // exact fp32 V
__device__ __half g_Ah[M_ * C_];         // fp16 attention output
__device__ __half g_Xh[M_ * C_];         // fp16 x
__device__ __half g_Wh[4 * C_ * C_];     // fp16 weights, TRANSPOSED [z][N][K]
__device__ float  g_m1[B_ * H_ * S_];
__device__ float  g_vs[B_ * H_ * DH_];
__device__ float  g_vsp[B_ * H_ * 8 * DH_];

__device__ __forceinline__ unsigned f2tf(float x) {
    unsigned r;
    asm("cvt.rna.tf32.f32 %0, %1;" : "=r"(r) : "f"(x));
    return r;
}

__device__ __forceinline__ uint32_t s2u(const void* p) {
    uint32_t a;
    asm("{ .reg .u64 t; cvta.to.shared.u64 t, %1; cvt.u32.u64 %0, t; }"
        : "=r"(a) : "l"(p));
    return a;
}

__device__ __forceinline__ void cp16(uint32_t d, const void* s) {
    asm volatile("cp.async.cg.shared.global [%0], [%1], 16;" :: "r"(d), "l"(s));
}
#define CP_COMMIT() asm volatile("cp.async.commit_group;" ::: "memory")
#define CP_WAIT2()  asm volatile("cp.async.wait_group 2;" ::: "memory")

// fp16 MMA: m16n8k16, fp32 accumulate
#define MMA_F16(c, a, b)                                                      \
    asm volatile(                                                             \
        "mma.sync.aligned.m16n8k16.row.col.f32.f16.f16.f32 "                  \
        "{%0,%1,%2,%3},{%4,%5,%6,%7},{%8,%9},{%0,%1,%2,%3};"                  \
        : "+f"((c)[0]), "+f"((c)[1]), "+f"((c)[2]), "+f"((c)[3])              \
        : "r"((a)[0]), "r"((a)[1]), "r"((a)[2]), "r"((a)[3]),                 \
          "r"((b)[0]), "r"((b)[1]))

// tf32 MMA (band GEMM2 only)
#define MMA_TF32(c, a, b)                                                     \
    asm volatile(                                                             \
        "mma.sync.aligned.m16n8k8.row.col.f32.tf32.tf32.f32 "                 \
        "{%0,%1,%2,%3},{%4,%5,%6,%7},{%8,%9},{%0,%1,%2,%3};"                  \
        : "+f"((c)[0]), "+f"((c)[1]), "+f"((c)[2]), "+f"((c)[3])              \
        : "r"((a)[0]), "r"((a)[1]), "r"((a)[2]), "r"((a)[3]),                 \
          "r"((b)[0]), "r"((b)[1]))

// ============================================================================
// x -> fp16
// ============================================================================
__global__ __launch_bounds__(256) void conv_x(
    const float* __restrict__ x, __half* __restrict__ Xh)
{
    const int i = blockIdx.x * 256 + threadIdx.x;   // float4 index
    float4 v = ((const float4*)x)[i];
    __half2 h0 = __floats2half2_rn(v.x, v.y);
    __half2 h1 = __floats2half2_rn(v.z, v.w);
    uint2 o;
    o.x = *(unsigned*)&h0;
    o.y = *(unsigned*)&h1;
    ((uint2*)Xh)[i] = o;
}

// ============================================================================
// Weight transpose + convert: Wh[z][n][k] = fp16(W_z[k][n])
// ============================================================================
__global__ __launch_bounds__(256) void trans_w(
    const float* __restrict__ W0, const float* __restrict__ W1,
    const float* __restrict__ W2, const float* __restrict__ W3,
    __half* __restrict__ Wh)
{
    __shared__ float t[32][33];
    const int z = blockIdx.z;
    const float* W = (z == 0) ? W0 : (z == 1) ? W1 : (z == 2) ? W2 : W3;
    __half* dst = Wh + (size_t)z * C_ * C_;
    const int n0 = blockIdx.x * 32;
    const int k0 = blockIdx.y * 32;
    const int tx = threadIdx.x & 31;
    const int ty = threadIdx.x >> 5;
#pragma unroll
    for (int i = 0; i < 4; ++i)
        t[ty + 8 * i][tx] = W[(k0 + ty + 8 * i) * C_ + n0 + tx];
    __syncthreads();
#pragma unroll
    for (int i = 0; i < 4; ++i)
        dst[(size_t)(n0 + ty + 8 * i) * C_ + k0 + tx] = __float2half_rn(t[tx][ty + 8 * i]);
}

// ============================================================================
// fp16 cp.async 3-stage GEMM: C = A[M,K]h @ Bt[N,K]h^T, fp32 accum.
// 128x128x32 tile, 8 warps (4x2), warp tile 32x64.
// smem: As[3][128][20]w + Bs[3][128][20]w = 61440 B (words hold half2 pairs).
// ============================================================================
#define HROW 20
#define HT_WORDS (128 * HROW)
#define HGEMM_SMEM_BYTES (6 * HT_WORDS * 4)

__device__ __forceinline__ void h_issue(
    const __half* __restrict__ A, const __half* __restrict__ B,
    int K, int bm, int bn, int kb, uint32_t sbase, int stage, int tid)
{
#pragma unroll
    for (int u = 0; u < 2; ++u) {
        const int f = tid + 256 * u;     // 0..511
        const int row = f >> 2;          // 0..127
        const int ch = f & 3;            // chunk of 8 halves
        cp16(sbase + (uint32_t)(stage * HT_WORDS + row * HROW + ch * 4) * 4,
             A + (size_t)(bm + row) * K + kb + ch * 8);
        cp16(sbase + (uint32_t)(3 * HT_WORDS + stage * HT_WORDS + row * HROW + ch * 4) * 4,
             B + (size_t)(bn + row) * K + kb + ch * 8);
    }
}

__device__ __forceinline__ void hgemm_body(
    const __half* __restrict__ A, const __half* __restrict__ B,
    float* __restrict__ Cf, __half* __restrict__ Ch, int N, int K)
{
    extern __shared__ unsigned smbuf[];
    const uint32_t sbase = s2u(smbuf);

    const int tid = threadIdx.x;
    const int bm = blockIdx.y * 128;
    const int bn = blockIdx.x * 128;

    const int wid  = tid >> 5;
    const int lane = tid & 31;
    const int g    = lane >> 2;
    const int tig  = lane & 3;
    const int warpM = wid >> 1;
    const int warpN = wid & 1;

    float c[2][8][4];
#pragma unroll
    for (int i = 0; i < 2; ++i)
#pragma unroll
        for (int j = 0; j < 8; ++j)
#pragma unroll
            for (int r = 0; r < 4; ++r) c[i][j][r] = 0.f;

    const int nt = K >> 5;   // 32-element K tiles

    h_issue(A, B, K, bm, bn, 0,  sbase, 0, tid); CP_COMMIT();
    h_issue(A, B, K, bm, bn, 32, sbase, 1, tid); CP_COMMIT();

    for (int t = 0; t < nt; ++t) {
        if (t + 2 < nt)
            h_issue(A, B, K, bm, bn, (t + 2) * 32, sbase, (t + 2) % 3, tid);
        CP_COMMIT();
        CP_WAIT2();
        __syncthreads();

        const unsigned* Ab = smbuf + (t % 3) * HT_WORDS;
        const unsigned* Bb = smbuf + 3 * HT_WORDS + (t % 3) * HT_WORDS;

#pragma unroll
        for (int ks = 0; ks < 2; ++ks) {
            const int k0 = ks * 8;   // word offset (16 halves per kstep)
            unsigned a[2][4];
#pragma unroll
            for (int m2 = 0; m2 < 2; ++m2) {
                const int mr = warpM * 32 + m2 * 16;
                a[m2][0] = Ab[(mr + g) * HROW + k0 + tig];
                a[m2][1] = Ab[(mr + g + 8) * HROW + k0 + tig];
                a[m2][2] = Ab[(mr + g) * HROW + k0 + tig + 4];
                a[m2][3] = Ab[(mr + g + 8) * HROW + k0 + tig + 4];
            }
#pragma unroll
            for (int j = 0; j < 8; ++j) {
                unsigned b[2];
                const int nc = warpN * 64 + j * 8 + g;
                b[0] = Bb[nc * HROW + k0 + tig];
                b[1] = Bb[nc * HROW + k0 + tig + 4];
                MMA_F16(c[0][j], a[0], b);
                MMA_F16(c[1][j], a[1], b);
            }
        }
        __syncthreads();
    }

#pragma unroll
    for (int m2 = 0; m2 < 2; ++m2) {
#pragma unroll
        for (int j = 0; j < 8; ++j) {
            const int row = bm + warpM * 32 + m2 * 16 + g;
            const int col = bn + warpN * 64 + j * 8 + 2 * tig;
            if (Ch) {
                __half2 h0 = __floats2half2_rn(c[m2][j][0], c[m2][j][1]);
                __half2 h1 = __floats2half2_rn(c[m2][j][2], c[m2][j][3]);
                *(__half2*)&Ch[(size_t)row * N + col]       = h0;
                *(__half2*)&Ch[(size_t)(row + 8) * N + col] = h1;
            } else {
                *(float2*)&Cf[(size_t)row * N + col] =
                    make_float2(c[m2][j][0], c[m2][j][1]);
                *(float2*)&Cf[(size_t)(row + 8) * N + col] =
                    make_float2(c[m2][j][2], c[m2][j][3]);
            }
        }
    }
}

__global__ __launch_bounds__(256, 2) void hgemm_out(
    const __half* __restrict__ A, const __half* __restrict__ B,
    float* __restrict__ C)
{
    hgemm_body(A, B, C, nullptr, C_, C_);
}

__global__ __launch_bounds__(256, 2) void hgemm_qkv(
    const __half* __restrict__ A, const __half* __restrict__ W,
    __half* __restrict__ Qh, __half* __restrict__ Kh, float* __restrict__ V)
{
    const int z = blockIdx.z;
    if (z == 0)      hgemm_body(A, W,                        nullptr, Qh, C_, C_);
    else if (z == 1) hgemm_body(A, W + (size_t)C_ * C_,      nullptr, Kh, C_, C_);
    else             hgemm_body(A, W + (size_t)2 * C_ * C_,  V, nullptr, C_, C_);
}

// ============================================================================
// fp16 score row-max: m1[bh][q] = max_k (q.k)/8. 64 q/block, 64-key tiles,
// double-buffered register prefetch. 4 ksteps of k16.
// ============================================================================
__global__ __launch_bounds__(256, 2) void score_max_h(
    const __half* __restrict__ Q, const __half* __restrict__ K,
    float* __restrict__ m1)
{
    __shared__ unsigned Ks[2][64][36];   // [key][d-pair], pad 36 (4g+tig mod32 ok)
    __shared__ float buf[4][64];

    const int bh = blockIdx.y;
    const int b = bh >> 4, h = bh & 15;
    const int q0 = blockIdx.x * 64;
    const int tid = threadIdx.x;
    const int rowbase = (b * S_) * C_ + h * DH_;

    const int wid  = tid >> 5;
    const int lane = tid & 31;
    const int g    = lane >> 2;
    const int tig  = lane & 3;
    const int warpM = wid & 3;
    const int warpN = wid >> 2;

    // stage Q tile into Ks[0] (plain fp16 copy), extract fragments
    {
#pragma unroll
        for (int u = 0; u < 2; ++u) {
            const int f = tid + 256 * u;     // 0..511 uint4 slots
            const int row = f >> 3;          // 0..63
            const int ch = f & 7;            // 8 halves each
            *(uint4*)&Ks[0][row][ch * 4] =
                *(const uint4*)(Q + rowbase + (q0 + row) * C_ + ch * 8);
        }
    }
    __syncthreads();

    unsigned bq[4][4][2];
#pragma unroll
    for (int na = 0; na < 4; ++na) {
        const int nc = warpN * 32 + na * 8 + g;
#pragma unroll
        for (int ks = 0; ks < 4; ++ks) {
            bq[na][ks][0] = Ks[0][nc][ks * 8 + tig];
            bq[na][ks][1] = Ks[0][nc][ks * 8 + tig + 4];
        }
    }
    __syncthreads();

    float rmax[4][2];
#pragma unroll
    for (int na = 0; na < 4; ++na) { rmax[na][0] = -1e30f; rmax[na][1] = -1e30f; }

    uint4 kv[2];
#pragma unroll
    for (int u = 0; u < 2; ++u) {
        const int f = tid + 256 * u;
        const int row = f >> 3, ch = f & 7;
        kv[u] = *(const uint4*)(K + rowbase + row * C_ + ch * 8);
    }

    for (int t = 0; t < S_ / 64; ++t) {
        const int cur = t & 1;
#pragma unroll
        for (int u = 0; u < 2; ++u) {
            const int f = tid + 256 * u;
            const int row = f >> 3, ch = f & 7;
            *(uint4*)&Ks[cur][row][ch * 4] = kv[u];
        }
        __syncthreads();

        if (t + 1 < S_ / 64) {
#pragma unroll
            for (int u = 0; u < 2; ++u) {
                const int f = tid + 256 * u;
                const int row = f >> 3, ch = f & 7;
                kv[u] = *(const uint4*)(K + rowbase + ((t + 1) * 64 + row) * C_ + ch * 8);
            }
        }

        float c[4][4];
#pragma unroll
        for (int na = 0; na < 4; ++na)
#pragma unroll
            for (int r = 0; r < 4; ++r) c[na][r] = 0.f;

        const int mr = warpM * 16;
#pragma unroll
        for (int ks = 0; ks < 4; ++ks) {
            const int k0 = ks * 8;
            unsigned a[4];
            a[0] = Ks[cur][mr + g][k0 + tig];
            a[1] = Ks[cur][mr + g + 8][k0 + tig];
            a[2] = Ks[cur][mr + g][k0 + tig + 4];
            a[3] = Ks[cur][mr + g + 8][k0 + tig + 4];
#pragma unroll
            for (int na = 0; na < 4; ++na)
                MMA_F16(c[na], a, bq[na][ks]);
        }

#pragma unroll
        for (int na = 0; na < 4; ++na) {
            rmax[na][0] = fmaxf(rmax[na][0], fmaxf(c[na][0], c[na][2]));
            rmax[na][1] = fmaxf(rmax[na][1], fmaxf(c[na][1], c[na][3]));
        }
    }

#pragma unroll
    for (int off = 4; off <= 16; off <<= 1)
#pragma unroll
        for (int na = 0; na < 4; ++na) {
            rmax[na][0] = fmaxf(rmax[na][0], __shfl_xor_sync(0xffffffffu, rmax[na][0], off));
            rmax[na][1] = fmaxf(rmax[na][1], __shfl_xor_sync(0xffffffffu, rmax[na][1], off));
        }

    if (g == 0) {
#pragma unroll
        for (int na = 0; na < 4; ++na) {
            buf[warpM][warpN * 32 + na * 8 + tig * 2 + 0] = rmax[na][0];
            buf[warpM][warpN * 32 + na * 8 + tig * 2 + 1] = rmax[na][1];
        }
    }
    __syncthreads();
    if (tid < 64) {
        float m = fmaxf(fmaxf(buf[0][tid], buf[1][tid]),
                        fmaxf(buf[2][tid], buf[3][tid]));
        m1[bh * S_ + q0 + tid] = m * 0.125f;
    }
}

// ============================================================================
// V column sums, two-stage (R12 winner, unchanged)
// ============================================================================
__global__ __launch_bounds__(256) void vsum_part(
    const float* __restrict__ V, float* __restrict__ vsp)
{
    __shared__ float red[4][64];
    const int bh = blockIdx.x;
    const int ch = blockIdx.y;
    const int b = bh >> 4, h = bh & 15;
    const int tid = threadIdx.x;
    const int d = tid & 63, grp = tid >> 6;
    const float* p = V + (b * S_) * C_ + h * DH_ + d;
    float s = 0.f;
    for (int k = ch * 256 + grp; k < ch * 256 + 256; k += 4) s += p[k * C_];
    red[grp][d] = s;
    __syncthreads();
    if (tid < 64)
        vsp[(bh * 8 + ch) * 64 + tid] =
            red[0][tid] + red[1][tid] + red[2][tid] + red[3][tid];
}

__global__ __launch_bounds__(64) void vsum_fin(
    const float* __restrict__ vsp, float* __restrict__ vs)
{
    const int bh = blockIdx.x;
    const int tid = threadIdx.x;
    float s = 0.f;
#pragma unroll
    for (int ch = 0; ch < 8; ++ch) s += vsp[(bh * 8 + ch) * 64 + tid];
    vs[bh * 64 + tid] = s;
}

// ============================================================================
// Banded attention: fp16 GEMM1 (4 ksteps), tf32 GEMM2 (unchanged math).
// Output stored fp16 for the out-projection.
// ============================================================================
__global__ __launch_bounds__(256) void band_attn_h(
    const __half* __restrict__ Q, const __half* __restrict__ K,
    const float* __restrict__ V, const float* __restrict__ m1,
    const float* __restrict__ vs, __half* __restrict__ Oh)
{
    __shared__ unsigned Qs[64][36];   // fp16 pairs
    __shared__ unsigned Ks[32][36];   // fp16 pairs
    __shared__ unsigned Vs[32][76];   // tf32
    __shared__ unsigned Ws[32][76];   // tf32
    __shared__ float zred[2][64];

    const int bh = blockIdx.y;
    const int b = bh >> 4, h = bh & 15;
    const int q0 = blockIdx.x * 64;
    const int tid = threadIdx.x;
    const int rowbase = (b * S_) * C_ + h * DH_;

    const int wid  = tid >> 5;
    const int lane = tid & 31;
    const int g    = lane >> 2;
    const int tig  = lane & 3;
    const int wm1 = wid & 1;
    const int wn1 = wid >> 1;
    const int wm2 = wid >> 1;
    const int wn2 = wid & 1;

    // load Q tile (fp16 plain copy)
    {
#pragma unroll
        for (int u = 0; u < 2; ++u) {
            const int f = tid + 256 * u;
            const int row = f >> 3;
            const int ch = f & 7;
            *(uint4*)&Qs[row][ch * 4] =
                *(const uint4*)(Q + rowbase + (q0 + row) * C_ + ch * 8);
        }
    }
    __syncthreads();

    unsigned bq[2][4][2];
#pragma unroll
    for (int na = 0; na < 2; ++na) {
        const int nc = wn1 * 16 + na * 8 + g;
#pragma unroll
        for (int ks = 0; ks < 4; ++ks) {
            bq[na][ks][0] = Qs[nc][ks * 8 + tig];
            bq[na][ks][1] = Qs[nc][ks * 8 + tig + 4];
        }
    }
    float m1c[2][2];
#pragma unroll
    for (int na = 0; na < 2; ++na) {
        const int qc = q0 + wn1 * 16 + na * 8 + 2 * tig;
        m1c[na][0] = m1[bh * S_ + qc];
        m1c[na][1] = m1[bh * S_ + qc + 1];
    }

    float o[4][4];
#pragma unroll
    for (int na = 0; na < 4; ++na)
#pragma unroll
        for (int r = 0; r < 4; ++r) o[na][r] = 0.f;
    float zp[2][2] = {{0.f, 0.f}, {0.f, 0.f}};

    const int klo  = (q0 >= 128) ? q0 - 128 : 0;
    const int kend = (q0 + 192 < S_) ? q0 + 192 : S_;

    for (int kt = klo; kt < kend; kt += 32) {
        __syncthreads();
        // K tile: 32x64 fp16 = 256 uint4, 1 per thread
        {
            const int row = tid >> 3;
            const int ch = tid & 7;
            *(uint4*)&Ks[row][ch * 4] =
                *(const uint4*)(K + rowbase + (kt + row) * C_ + ch * 8);
        }
        // V tile: 32x64 fp32 -> tf32, 2 float4 per thread
        {
#pragma unroll
            for (int u = 0; u < 2; ++u) {
                const int f = tid + 256 * u;
                const int r = f >> 4;
                const int c4 = (f & 15) * 4;
                float4 c = *(const float4*)(V + rowbase + (kt + r) * C_ + c4);
                uint4 tc;
                tc.x = f2tf(c.x); tc.y = f2tf(c.y); tc.z = f2tf(c.z); tc.w = f2tf(c.w);
                *(uint4*)&Vs[r][c4] = tc;
            }
        }
        __syncthreads();

        // ---- GEMM1 (fp16): S^T[key][q] ----
        float s[2][4];
#pragma unroll
        for (int na = 0; na < 2; ++na)
#pragma unroll
            for (int r = 0; r < 4; ++r) s[na][r] = 0.f;

        const int mr1 = wm1 * 16;
#pragma unroll
        for (int ks = 0; ks < 4; ++ks) {
            const int k0 = ks * 8;
            unsigned a[4];
            a[0] = Ks[mr1 + g][k0 + tig];
            a[1] = Ks[mr1 + g + 8][k0 + tig];
            a[2] = Ks[mr1 + g][k0 + tig + 4];
            a[3] = Ks[mr1 + g + 8][k0 + tig + 4];
            MMA_F16(s[0], a, bq[0][ks]);
            MMA_F16(s[1], a, bq[1][ks]);
        }

        // ---- exp / band mask / Z -> W^T (tf32) ----
#pragma unroll
        for (int na = 0; na < 2; ++na) {
            const int colq = wn1 * 16 + na * 8 + 2 * tig;
#pragma unroll
            for (int r2 = 0; r2 < 2; ++r2) {
                const int keyrow = wm1 * 16 + g + r2 * 8;
                const int key = kt + keyrow;
#pragma unroll
                for (int j = 0; j < 2; ++j) {
                    const float sv = s[na][r2 * 2 + j];
                    const int d = key - (q0 + colq + j);
                    float tt = __expf(sv * 0.125f - m1c[na][j]);
                    float w = __expf(tt) - 1.0f;
                    if (d < -128 || d > 127) w = 0.f;
                    const unsigned wt = f2tf(w);
                    zp[na][j] += __uint_as_float(wt);
                    Ws[keyrow][colq + j] = wt;
                }
            }
        }
        __syncthreads();

        // ---- GEMM2 (tf32): O += W @ V ----
        const int mr2 = wm2 * 16;
#pragma unroll
        for (int ks = 0; ks < 4; ++ks) {
            const int k0 = ks * 8;
            unsigned a[4];
            a[0] = Ws[k0 + tig][mr2 + g];
            a[1] = Ws[k0 + tig][mr2 + g + 8];
            a[2] = Ws[k0 + tig + 4][mr2 + g];
            a[3] = Ws[k0 + tig + 4][mr2 + g + 8];
#pragma unroll
            for (int na = 0; na < 4; ++na) {
                unsigned bb[2];
                const int nc = wn2 * 32 + na * 8 + g;
                bb[0] = Vs[k0 + tig][nc];
                bb[1] = Vs[k0 + tig + 4][nc];
                MMA_TF32(o[na], a, bb);
            }
        }
    }

#pragma unroll
    for (int off = 4; off <= 16; off <<= 1)
#pragma unroll
        for (int na = 0; na < 2; ++na) {
            zp[na][0] += __shfl_xor_sync(0xffffffffu, zp[na][0], off);
            zp[na][1] += __shfl_xor_sync(0xffffffffu, zp[na][1], off);
        }
    if (g == 0) {
#pragma unroll
        for (int na = 0; na < 2; ++na) {
            zred[wm1][wn1 * 16 + na * 8 + 2 * tig + 0] = zp[na][0];
            zred[wm1][wn1 * 16 + na * 8 + 2 * tig + 1] = zp[na][1];
        }
    }
    __syncthreads();

    const float* vsp = vs + bh * 64;
#pragma unroll
    for (int r2 = 0; r2 < 2; ++r2) {
        const int row = wm2 * 16 + g + r2 * 8;
        const float inv = 1.0f / ((float)S_ + zred[0][row] + zred[1][row]);
        __half* op = Oh + rowbase + (q0 + row) * C_;
#pragma unroll
        for (int na = 0; na < 4; ++na) {
            const int col = wn2 * 32 + na * 8 + 2 * tig;
            __half2 hv = __floats2half2_rn((o[na][r2 * 2 + 0] + vsp[col])     * inv,
                                           (o[na][r2 * 2 + 1] + vsp[col + 1]) * inv);
            *(__half2*)(op + col) = hv;
        }
    }
}

// ============================================================================
extern "C" void kernel_launch(void* const* d_in, const int* in_sizes, int n_in,
                              void* d_out, int out_size)
{
    (void)in_sizes; (void)n_in; (void)out_size;
    const float* x  = (const float*)d_in[0];
    const float* Wq = (const float*)d_in[1];
    const float* Wk = (const float*)d_in[2];
    const float* Wv = (const float*)d_in[3];
    const float* Wo = (const float*)d_in[4];
    float* out = (float*)d_out;

    __half *Qhp, *Khp, *Ahp, *Xhp, *Whp;
    float *Vp, *m1p, *vsp, *vspp;
    cudaGetSymbolAddress((void**)&Qhp, g_Qh);
    cudaGetSymbolAddress((void**)&Khp, g_Kh);
    cudaGetSymbolAddress((void**)&Vp,  g_V);
    cudaGetSymbolAddress((void**)&Ahp, g_Ah);
    cudaGetSymbolAddress((void**)&Xhp, g_Xh);
    cudaGetSymbolAddress((void**)&Whp, g_Wh);
    cudaGetSymbolAddress((void**)&m1p, g_m1);
    cudaGetSymbolAddress((void**)&vsp, g_vs);
    cudaGetSymbolAddress((void**)&vspp, g_vsp);

    cudaFuncSetAttribute(hgemm_out,
                         cudaFuncAttributeMaxDynamicSharedMemorySize,
                         HGEMM_SMEM_BYTES);
    cudaFuncSetAttribute(hgemm_qkv,
                         cudaFuncAttributeMaxDynamicSharedMemorySize,
                         HGEMM_SMEM_BYTES);

    conv_x<<<(M_ * C_ / 4) / 256, 256>>>(x, Xhp);
    trans_w<<<dim3(32, 32, 4), 256>>>(Wq, Wk, Wv, Wo, Whp);

    dim3 gq(C_ / 128, M_ / 128, 3);         // (8, 32, 3)
    hgemm_qkv<<<gq, 256, HGEMM_SMEM_BYTES>>>(Xhp, Whp, Qhp, Khp, Vp);

    score_max_h<<<dim3(S_ / 64, B_ * H_), 256>>>(Qhp, Khp, m1p);
    vsum_part<<<dim3(B_ * H_, 8), 256>>>(Vp, vspp);
    vsum_fin<<<B_ * H_, 64>>>(vspp, vsp);
    band_attn_h<<<dim3(S_ / 64, B_ * H_), 256>>>(Qhp, Khp, Vp, m1p, vsp, Ahp);

    dim3 gg(C_ / 128, M_ / 128);            // (8, 32)
    hgemm_out<<<gg, 256, HGEMM_SMEM_BYTES>>>(Ahp, Whp + (size_t)3 * C_ * C_, out);
}

// round 15
// speedup vs baseline: 1.8180x; 1.0143x over previous
#include <cuda_runtime.h>
#include <cuda_fp16.h>
#include <math.h>
#include <cstdint>

#define B_   2
#define S_   2048
#define C_   1024
#define H_   16
#define DH_  64
#define M_   (B_ * S_)       // 4096 rows

// ---- scratch (device globals; no allocation allowed) ----
__device__ __half g_Qh[M_ * C_];         // fp16 Q (GEMM epilogue)
__device__ __half g_Kh[M_ * C_];         // fp16 K
__device__ float  g_V [M_ * C_];         // exact fp32 V
__device__ __half g_Ah[M_ * C_];         // fp16 attention output
__device__ __half g_Xh[M_ * C_];         // fp16 x
__device__ __half g_Wh[4 * C_ * C_];     // fp16 weights, TRANSPOSED [z][N][K]
__device__ float  g_m1[B_ * H_ * S_];
__device__ float  g_vs[B_ * H_ * DH_];
__device__ float  g_vsp[B_ * H_ * 8 * DH_];

__device__ __forceinline__ uint32_t s2u(const void* p) {
    uint32_t a;
    asm("{ .reg .u64 t; cvta.to.shared.u64 t, %1; cvt.u32.u64 %0, t; }"
        : "=r"(a) : "l"(p));
    return a;
}

__device__ __forceinline__ void cp16(uint32_t d, const void* s) {
    asm volatile("cp.async.cg.shared.global [%0], [%1], 16;" :: "r"(d), "l"(s));
}
#define CP_COMMIT() asm volatile("cp.async.commit_group;" ::: "memory")
#define CP_WAIT2()  asm volatile("cp.async.wait_group 2;" ::: "memory")

// fp16 MMA: m16n8k16, fp32 accumulate
#define MMA_F16(c, a, b)                                                      \
    asm volatile(                                                             \
        "mma.sync.aligned.m16n8k16.row.col.f32.f16.f16.f32 "                  \
        "{%0,%1,%2,%3},{%4,%5,%6,%7},{%8,%9},{%0,%1,%2,%3};"                  \
        : "+f"((c)[0]), "+f"((c)[1]), "+f"((c)[2]), "+f"((c)[3])              \
        : "r"((a)[0]), "r"((a)[1]), "r"((a)[2]), "r"((a)[3]),                 \
          "r"((b)[0]), "r"((b)[1]))

// ============================================================================
// x -> fp16
// ============================================================================
__global__ __launch_bounds__(256) void conv_x(
    const float* __restrict__ x, __half* __restrict__ Xh)
{
    const int i = blockIdx.x * 256 + threadIdx.x;
    float4 v = ((const float4*)x)[i];
    __half2 h0 = __floats2half2_rn(v.x, v.y);
    __half2 h1 = __floats2half2_rn(v.z, v.w);
    uint2 o;
    o.x = *(unsigned*)&h0;
    o.y = *(unsigned*)&h1;
    ((uint2*)Xh)[i] = o;
}

// ============================================================================
// Weight transpose + convert: Wh[z][n][k] = fp16(W_z[k][n])
// ============================================================================
__global__ __launch_bounds__(256) void trans_w(
    const float* __restrict__ W0, const float* __restrict__ W1,
    const float* __restrict__ W2, const float* __restrict__ W3,
    __half* __restrict__ Wh)
{
    __shared__ float t[32][33];
    const int z = blockIdx.z;
    const float* W = (z == 0) ? W0 : (z == 1) ? W1 : (z == 2) ? W2 : W3;
    __half* dst = Wh + (size_t)z * C_ * C_;
    const int n0 = blockIdx.x * 32;
    const int k0 = blockIdx.y * 32;
    const int tx = threadIdx.x & 31;
    const int ty = threadIdx.x >> 5;
#pragma unroll
    for (int i = 0; i < 4; ++i)
        t[ty + 8 * i][tx] = W[(k0 + ty + 8 * i) * C_ + n0 + tx];
    __syncthreads();
#pragma unroll
    for (int i = 0; i < 4; ++i)
        dst[(size_t)(n0 + ty + 8 * i) * C_ + k0 + tx] = __float2half_rn(t[tx][ty + 8 * i]);
}

// ============================================================================
// fp16 cp.async 3-stage GEMM (R14 winner, unchanged)
// ============================================================================
#define HROW 20
#define HT_WORDS (128 * HROW)
#define HGEMM_SMEM_BYTES (6 * HT_WORDS * 4)

__device__ __forceinline__ void h_issue(
    const __half* __restrict__ A, const __half* __restrict__ B,
    int K, int bm, int bn, int kb, uint32_t sbase, int stage, int tid)
{
#pragma unroll
    for (int u = 0; u < 2; ++u) {
        const int f = tid + 256 * u;
        const int row = f >> 2;
        const int ch = f & 3;
        cp16(sbase + (uint32_t)(stage * HT_WORDS + row * HROW + ch * 4) * 4,
             A + (size_t)(bm + row) * K + kb + ch * 8);
        cp16(sbase + (uint32_t)(3 * HT_WORDS + stage * HT_WORDS + row * HROW + ch * 4) * 4,
             B + (size_t)(bn + row) * K + kb + ch * 8);
    }
}

__device__ __forceinline__ void hgemm_body(
    const __half* __restrict__ A, const __half* __restrict__ B,
    float* __restrict__ Cf, __half* __restrict__ Ch, int N, int K)
{
    extern __shared__ unsigned smbuf[];
    const uint32_t sbase = s2u(smbuf);

    const int tid = threadIdx.x;
    const int bm = blockIdx.y * 128;
    const int bn = blockIdx.x * 128;

    const int wid  = tid >> 5;
    const int lane = tid & 31;
    const int g    = lane >> 2;
    const int tig  = lane & 3;
    const int warpM = wid >> 1;
    const int warpN = wid & 1;

    float c[2][8][4];
#pragma unroll
    for (int i = 0; i < 2; ++i)
#pragma unroll
        for (int j = 0; j < 8; ++j)
#pragma unroll
            for (int r = 0; r < 4; ++r) c[i][j][r] = 0.f;

    const int nt = K >> 5;

    h_issue(A, B, K, bm, bn, 0,  sbase, 0, tid); CP_COMMIT();
    h_issue(A, B, K, bm, bn, 32, sbase, 1, tid); CP_COMMIT();

    for (int t = 0; t < nt; ++t) {
        if (t + 2 < nt)
            h_issue(A, B, K, bm, bn, (t + 2) * 32, sbase, (t + 2) % 3, tid);
        CP_COMMIT();
        CP_WAIT2();
        __syncthreads();

        const unsigned* Ab = smbuf + (t % 3) * HT_WORDS;
        const unsigned* Bb = smbuf + 3 * HT_WORDS + (t % 3) * HT_WORDS;

#pragma unroll
        for (int ks = 0; ks < 2; ++ks) {
            const int k0 = ks * 8;
            unsigned a[2][4];
#pragma unroll
            for (int m2 = 0; m2 < 2; ++m2) {
                const int mr = warpM * 32 + m2 * 16;
                a[m2][0] = Ab[(mr + g) * HROW + k0 + tig];
                a[m2][1] = Ab[(mr + g + 8) * HROW + k0 + tig];
                a[m2][2] = Ab[(mr + g) * HROW + k0 + tig + 4];
                a[m2][3] = Ab[(mr + g + 8) * HROW + k0 + tig + 4];
            }
#pragma unroll
            for (int j = 0; j < 8; ++j) {
                unsigned b[2];
                const int nc = warpN * 64 + j * 8 + g;
                b[0] = Bb[nc * HROW + k0 + tig];
                b[1] = Bb[nc * HROW + k0 + tig + 4];
                MMA_F16(c[0][j], a[0], b);
                MMA_F16(c[1][j], a[1], b);
            }
        }
        __syncthreads();
    }

#pragma unroll
    for (int m2 = 0; m2 < 2; ++m2) {
#pragma unroll
        for (int j = 0; j < 8; ++j) {
            const int row = bm + warpM * 32 + m2 * 16 + g;
            const int col = bn + warpN * 64 + j * 8 + 2 * tig;
            if (Ch) {
                __half2 h0 = __floats2half2_rn(c[m2][j][0], c[m2][j][1]);
                __half2 h1 = __floats2half2_rn(c[m2][j][2], c[m2][j][3]);
                *(__half2*)&Ch[(size_t)row * N + col]       = h0;
                *(__half2*)&Ch[(size_t)(row + 8) * N + col] = h1;
            } else {
                *(float2*)&Cf[(size_t)row * N + col] =
                    make_float2(c[m2][j][0], c[m2][j][1]);
                *(float2*)&Cf[(size_t)(row + 8) * N + col] =
                    make_float2(c[m2][j][2], c[m2][j][3]);
            }
        }
    }
}

__global__ __launch_bounds__(256, 2) void hgemm_out(
    const __half* __restrict__ A, const __half* __restrict__ B,
    float* __restrict__ C)
{
    hgemm_body(A, B, C, nullptr, C_, C_);
}

__global__ __launch_bounds__(256, 2) void hgemm_qkv(
    const __half* __restrict__ A, const __half* __restrict__ W,
    __half* __restrict__ Qh, __half* __restrict__ Kh, float* __restrict__ V)
{
    const int z = blockIdx.z;
    if (z == 0)      hgemm_body(A, W,                        nullptr, Qh, C_, C_);
    else if (z == 1) hgemm_body(A, W + (size_t)C_ * C_,      nullptr, Kh, C_, C_);
    else             hgemm_body(A, W + (size_t)2 * C_ * C_,  V, nullptr, C_, C_);
}

// ============================================================================
// fp16 score row-max (R14 winner, unchanged)
// ============================================================================
__global__ __launch_bounds__(256, 2) void score_max_h(
    const __half* __restrict__ Q, const __half* __restrict__ K,
    float* __restrict__ m1)
{
    __shared__ unsigned Ks[2][64][36];
    __shared__ float buf[4][64];

    const int bh = blockIdx.y;
    const int b = bh >> 4, h = bh & 15;
    const int q0 = blockIdx.x * 64;
    const int tid = threadIdx.x;
    const int rowbase = (b * S_) * C_ + h * DH_;

    const int wid  = tid >> 5;
    const int lane = tid & 31;
    const int g    = lane >> 2;
    const int tig  = lane & 3;
    const int warpM = wid & 3;
    const int warpN = wid >> 2;

    {
#pragma unroll
        for (int u = 0; u < 2; ++u) {
            const int f = tid + 256 * u;
            const int row = f >> 3;
            const int ch = f & 7;
            *(uint4*)&Ks[0][row][ch * 4] =
                *(const uint4*)(Q + rowbase + (q0 + row) * C_ + ch * 8);
        }
    }
    __syncthreads();

    unsigned bq[4][4][2];
#pragma unroll
    for (int na = 0; na < 4; ++na) {
        const int nc = warpN * 32 + na * 8 + g;
#pragma unroll
        for (int ks = 0; ks < 4; ++ks) {
            bq[na][ks][0] = Ks[0][nc][ks * 8 + tig];
            bq[na][ks][1] = Ks[0][nc][ks * 8 + tig + 4];
        }
    }
    __syncthreads();

    float rmax[4][2];
#pragma unroll
    for (int na = 0; na < 4; ++na) { rmax[na][0] = -1e30f; rmax[na][1] = -1e30f; }

    uint4 kv[2];
#pragma unroll
    for (int u = 0; u < 2; ++u) {
        const int f = tid + 256 * u;
        const int row = f >> 3, ch = f & 7;
        kv[u] = *(const uint4*)(K + rowbase + row * C_ + ch * 8);
    }

    for (int t = 0; t < S_ / 64; ++t) {
        const int cur = t & 1;
#pragma unroll
        for (int u = 0; u < 2; ++u) {
            const int f = tid + 256 * u;
            const int row = f >> 3, ch = f & 7;
            *(uint4*)&Ks[cur][row][ch * 4] = kv[u];
        }
        __syncthreads();

        if (t + 1 < S_ / 64) {
#pragma unroll
            for (int u = 0; u < 2; ++u) {
                const int f = tid + 256 * u;
                const int row = f >> 3, ch = f & 7;
                kv[u] = *(const uint4*)(K + rowbase + ((t + 1) * 64 + row) * C_ + ch * 8);
            }
        }

        float c[4][4];
#pragma unroll
        for (int na = 0; na < 4; ++na)
#pragma unroll
            for (int r = 0; r < 4; ++r) c[na][r] = 0.f;

        const int mr = warpM * 16;
#pragma unroll
        for (int ks = 0; ks < 4; ++ks) {
            const int k0 = ks * 8;
            unsigned a[4];
            a[0] = Ks[cur][mr + g][k0 + tig];
            a[1] = Ks[cur][mr + g + 8][k0 + tig];
            a[2] = Ks[cur][mr + g][k0 + tig + 4];
            a[3] = Ks[cur][mr + g + 8][k0 + tig + 4];
#pragma unroll
            for (int na = 0; na < 4; ++na)
                MMA_F16(c[na], a, bq[na][ks]);
        }

#pragma unroll
        for (int na = 0; na < 4; ++na) {
            rmax[na][0] = fmaxf(rmax[na][0], fmaxf(c[na][0], c[na][2]));
            rmax[na][1] = fmaxf(rmax[na][1], fmaxf(c[na][1], c[na][3]));
        }
    }

#pragma unroll
    for (int off = 4; off <= 16; off <<= 1)
#pragma unroll
        for (int na = 0; na < 4; ++na) {
            rmax[na][0] = fmaxf(rmax[na][0], __shfl_xor_sync(0xffffffffu, rmax[na][0], off));
            rmax[na][1] = fmaxf(rmax[na][1], __shfl_xor_sync(0xffffffffu, rmax[na][1], off));
        }

    if (g == 0) {
#pragma unroll
        for (int na = 0; na < 4; ++na) {
            buf[warpM][warpN * 32 + na * 8 + tig * 2 + 0] = rmax[na][0];
            buf[warpM][warpN * 32 + na * 8 + tig * 2 + 1] = rmax[na][1];
        }
    }
    __syncthreads();
    if (tid < 64) {
        float m = fmaxf(fmaxf(buf[0][tid], buf[1][tid]),
                        fmaxf(buf[2][tid], buf[3][tid]));
        m1[bh * S_ + q0 + tid] = m * 0.125f;
    }
}

// ============================================================================
// V column sums, two-stage (unchanged)
// ============================================================================
__global__ __launch_bounds__(256) void vsum_part(
    const float* __restrict__ V, float* __restrict__ vsp)
{
    __shared__ float red[4][64];
    const int bh = blockIdx.x;
    const int ch = blockIdx.y;
    const int b = bh >> 4, h = bh & 15;
    const int tid = threadIdx.x;
    const int d = tid & 63, grp = tid >> 6;
    const float* p = V + (b * S_) * C_ + h * DH_ + d;
    float s = 0.f;
    for (int k = ch * 256 + grp; k < ch * 256 + 256; k += 4) s += p[k * C_];
    red[grp][d] = s;
    __syncthreads();
    if (tid < 64)
        vsp[(bh * 8 + ch) * 64 + tid] =
            red[0][tid] + red[1][tid] + red[2][tid] + red[3][tid];
}

__global__ __launch_bounds__(64) void vsum_fin(
    const float* __restrict__ vsp, float* __restrict__ vs)
{
    const int bh = blockIdx.x;
    const int tid = threadIdx.x;
    float s = 0.f;
#pragma unroll
    for (int ch = 0; ch < 8; ++ch) s += vsp[(bh * 8 + ch) * 64 + tid];
    vs[bh * 64 + tid] = s;
}

// ============================================================================
// FA2-style banded attention, all fp16 MMAs, W kept in registers.
// Per block: 64 q. GEMM1: S[q][key] = Q @ K^T (m=q: warpM=wid&3 over 4x16 q;
// n=32 keys: warpN=wid>>2 over 2x16). c fragment -> half2 A fragment of
// GEMM2 directly. GEMM2: partial O[16q][64d] over warp's 16-key slice
// (8 n-atoms, 1 kstep); cross-warpN add in epilogue via smem.
// ============================================================================
__global__ __launch_bounds__(256) void band_attn_h(
    const __half* __restrict__ Q, const __half* __restrict__ K,
    const float* __restrict__ V, const float* __restrict__ m1,
    const float* __restrict__ vs, __half* __restrict__ Oh)
{
    __shared__ unsigned Qs[64][36];     // fp16 pairs [q][d]
    __shared__ unsigned Ks[32][36];     // fp16 pairs [key][d]
    __shared__ __half  Vt[64][40];      // fp16 [d][key] (transposed)
    __shared__ float   obuf[64][66];    // warpN=0 partial O
    __shared__ float   zred[2][64];

    const int bh = blockIdx.y;
    const int b = bh >> 4, h = bh & 15;
    const int q0 = blockIdx.x * 64;
    const int tid = threadIdx.x;
    const int rowbase = (b * S_) * C_ + h * DH_;

    const int wid  = tid >> 5;
    const int lane = tid & 31;
    const int g    = lane >> 2;
    const int tig  = lane & 3;
    const int warpM = wid & 3;     // 4x16 queries
    const int warpN = wid >> 2;    // 2x16 keys

    // load Q tile (fp16 plain copy)
#pragma unroll
    for (int u = 0; u < 2; ++u) {
        const int f = tid + 256 * u;
        const int row = f >> 3;
        const int ch = f & 7;
        *(uint4*)&Qs[row][ch * 4] =
            *(const uint4*)(Q + rowbase + (q0 + row) * C_ + ch * 8);
    }
    __syncthreads();

    // hoist Q A-fragments (m rows = warpM*16)
    unsigned aq[4][4];
    const int mr = warpM * 16;
#pragma unroll
    for (int kk = 0; kk < 4; ++kk) {
        aq[kk][0] = Qs[mr + g][kk * 8 + tig];
        aq[kk][1] = Qs[mr + g + 8][kk * 8 + tig];
        aq[kk][2] = Qs[mr + g][kk * 8 + tig + 4];
        aq[kk][3] = Qs[mr + g + 8][kk * 8 + tig + 4];
    }
    float m1row[2];
    m1row[0] = m1[bh * S_ + q0 + mr + g];
    m1row[1] = m1[bh * S_ + q0 + mr + g + 8];

    float o[8][4];
#pragma unroll
    for (int na = 0; na < 8; ++na)
#pragma unroll
        for (int r = 0; r < 4; ++r) o[na][r] = 0.f;
    float zp[2] = {0.f, 0.f};

    const int klo  = (q0 >= 128) ? q0 - 128 : 0;
    const int kend = (q0 + 192 < S_) ? q0 + 192 : S_;

    for (int kt = klo; kt < kend; kt += 32) {
        __syncthreads();   // prev GEMM2 done reading Ks/Vt
        // K tile: 32x64 fp16, 1 uint4/thread
        {
            const int row = tid >> 3;
            const int ch = tid & 7;
            *(uint4*)&Ks[row][ch * 4] =
                *(const uint4*)(K + rowbase + (kt + row) * C_ + ch * 8);
        }
        // V tile: fp32 [key][d] -> fp16 transposed Vt[d][key]
#pragma unroll
        for (int u = 0; u < 2; ++u) {
            const int f = tid + 256 * u;
            const int r = f >> 4;            // key 0..31
            const int c4 = (f & 15) * 4;     // d base
            float4 c = *(const float4*)(V + rowbase + (kt + r) * C_ + c4);
            Vt[c4 + 0][r] = __float2half_rn(c.x);
            Vt[c4 + 1][r] = __float2half_rn(c.y);
            Vt[c4 + 2][r] = __float2half_rn(c.z);
            Vt[c4 + 3][r] = __float2half_rn(c.w);
        }
        __syncthreads();

        // ---- GEMM1: S[q][key], n = warpN's 16 keys (2 atoms) ----
        float c[2][4];
#pragma unroll
        for (int na = 0; na < 2; ++na)
#pragma unroll
            for (int r = 0; r < 4; ++r) c[na][r] = 0.f;

#pragma unroll
        for (int kk = 0; kk < 4; ++kk) {
            const int k0 = kk * 8;
#pragma unroll
            for (int na = 0; na < 2; ++na) {
                unsigned bb[2];
                const int nc = warpN * 16 + na * 8 + g;
                bb[0] = Ks[nc][k0 + tig];
                bb[1] = Ks[nc][k0 + tig + 4];
                MMA_F16(c[na], aq[kk], bb);
            }
        }

        // ---- exp / band mask / Z; pack W fragments in registers ----
        unsigned aw[4];
#pragma unroll
        for (int na = 0; na < 2; ++na) {
#pragma unroll
            for (int r2 = 0; r2 < 2; ++r2) {
                const int q = q0 + mr + g + r2 * 8;
                __half wh[2];
#pragma unroll
                for (int j = 0; j < 2; ++j) {
                    const int key = kt + warpN * 16 + na * 8 + 2 * tig + j;
                    const float sv = c[na][r2 * 2 + j];
                    const int d = key - q;
                    float tt = __expf(sv * 0.125f - m1row[r2]);
                    float w = __expf(tt) - 1.0f;
                    if (d < -128 || d > 127) w = 0.f;
                    wh[j] = __float2half_rn(w);
                    zp[r2] += __half2float(wh[j]);
                }
                __half2 p = __halves2half2(wh[0], wh[1]);
                aw[na * 2 + r2] = *(unsigned*)&p;
            }
        }
        // aw index: a[0]=(row g, k 2tig) = aw[0]; a[1]=(row g+8) = aw[1];
        //           a[2]=(row g, k 8+2tig) = aw[2]; a[3] = aw[3]
        unsigned afrag[4] = { aw[0], aw[1], aw[2], aw[3] };

        // ---- GEMM2: partial O[16q][64d] over warp's 16 keys (1 kstep) ----
#pragma unroll
        for (int na = 0; na < 8; ++na) {
            unsigned bv[2];
            const int nc2 = na * 8 + g;      // d column
            const unsigned* vw = (const unsigned*)&Vt[nc2][0];
            bv[0] = vw[warpN * 8 + tig];
            bv[1] = vw[warpN * 8 + tig + 4];
            MMA_F16(o[na], afrag, bv);
        }
    }

    // ---- Z reduce: over tig lanes (xor 1,2), then across warpN via smem ----
#pragma unroll
    for (int off = 1; off <= 2; off <<= 1) {
        zp[0] += __shfl_xor_sync(0xffffffffu, zp[0], off);
        zp[1] += __shfl_xor_sync(0xffffffffu, zp[1], off);
    }
    if (tig == 0) {
        zred[warpN][mr + g]     = zp[0];
        zred[warpN][mr + g + 8] = zp[1];
    }

    // ---- O cross-warpN reduction + epilogue ----
    __syncthreads();
    if (warpN == 0) {
#pragma unroll
        for (int na = 0; na < 8; ++na) {
            const int col = na * 8 + 2 * tig;
            *(float2*)&obuf[mr + g][col]     = make_float2(o[na][0], o[na][1]);
            *(float2*)&obuf[mr + g + 8][col] = make_float2(o[na][2], o[na][3]);
        }
    }
    __syncthreads();
    if (warpN == 1) {
        const float* vsp = vs + bh * 64;
#pragma unroll
        for (int r2 = 0; r2 < 2; ++r2) {
            const int row = mr + g + r2 * 8;
            const float inv = 1.0f / ((float)S_ + zred[0][row] + zred[1][row]);
            __half* op = Oh + rowbase + (q0 + row) * C_;
#pragma unroll
            for (int na = 0; na < 8; ++na) {
                const int col = na * 8 + 2 * tig;
                float v0 = (o[na][r2 * 2 + 0] + obuf[row][col]     + vsp[col])     * inv;
                float v1 = (o[na][r2 * 2 + 1] + obuf[row][col + 1] + vsp[col + 1]) * inv;
                *(__half2*)(op + col) = __floats2half2_rn(v0, v1);
            }
        }
    }
}

// ============================================================================
extern "C" void kernel_launch(void* const* d_in, const int* in_sizes, int n_in,
                              void* d_out, int out_size)
{
    (void)in_sizes; (void)n_in; (void)out_size;
    const float* x  = (const float*)d_in[0];
    const float* Wq = (const float*)d_in[1];
    const float* Wk = (const float*)d_in[2];
    const float* Wv = (const float*)d_in[3];
    const float* Wo = (const float*)d_in[4];
    float* out = (float*)d_out;

    __half *Qhp, *Khp, *Ahp, *Xhp, *Whp;
    float *Vp, *m1p, *vsp, *vspp;
    cudaGetSymbolAddress((void**)&Qhp, g_Qh);
    cudaGetSymbolAddress((void**)&Khp, g_Kh);
    cudaGetSymbolAddress((void**)&Vp,  g_V);
    cudaGetSymbolAddress((void**)&Ahp, g_Ah);
    cudaGetSymbolAddress((void**)&Xhp, g_Xh);
    cudaGetSymbolAddress((void**)&Whp, g_Wh);
    cudaGetSymbolAddress((void**)&m1p, g_m1);
    cudaGetSymbolAddress((void**)&vsp, g_vs);
    cudaGetSymbolAddress((void**)&vspp, g_vsp);

    cudaFuncSetAttribute(hgemm_out,
                         cudaFuncAttributeMaxDynamicSharedMemorySize,
                         HGEMM_SMEM_BYTES);
    cudaFuncSetAttribute(hgemm_qkv,
                         cudaFuncAttributeMaxDynamicSharedMemorySize,
                         HGEMM_SMEM_BYTES);

    conv_x<<<(M_ * C_ / 4) / 256, 256>>>(x, Xhp);
    trans_w<<<dim3(32, 32, 4), 256>>>(Wq, Wk, Wv, Wo, Whp);

    dim3 gq(C_ / 128, M_ / 128, 3);         // (8, 32, 3)
    hgemm_qkv<<<gq, 256, HGEMM_SMEM_BYTES>>>(Xhp, Whp, Qhp, Khp, Vp);

    score_max_h<<<dim3(S_ / 64, B_ * H_), 256>>>(Qhp, Khp, m1p);
    vsum_part<<<dim3(B_ * H_, 8), 256>>>(Vp, vspp);
    vsum_fin<<<B_ * H_, 64>>>(vspp, vsp);
    band_attn_h<<<dim3(S_ / 64, B_ * H_), 256>>>(Qhp, Khp, Vp, m1p, vsp, Ahp);

    dim3 gg(C_ / 128, M_ / 128);            // (8, 32)
    hgemm_out<<<gg, 256, HGEMM_SMEM_BYTES>>>(Ahp, Whp + (size_t)3 * C_ * C_, out);
}

// round 16
// speedup vs baseline: 1.8841x; 1.0364x over previous
#include <cuda_runtime.h>
#include <cuda_fp16.h>
#include <math.h>
#include <cstdint>

#define B_   2
#define S_   2048
#define C_   1024
#define H_   16
#define DH_  64
#define M_   (B_ * S_)       // 4096 rows

// ---- scratch (device globals; no allocation allowed) ----
__device__ __half g_Qh[M_ * C_];         // fp16 Q (GEMM epilogue)
__device__ __half g_Kh[M_ * C_];         // fp16 K
__device__ float  g_V [M_ * C_];         // exact fp32 V
__device__ __half g_Ah[M_ * C_];         // fp16 attention output
__device__ __half g_Xh[M_ * C_];         // fp16 x
__device__ __half g_Wh[4 * C_ * C_];     // fp16 weights, TRANSPOSED [z][N][K]
__device__ float  g_m1[B_ * H_ * S_];
__device__ float  g_vs[B_ * H_ * DH_];
__device__ float  g_vsp[B_ * H_ * 8 * DH_];

__device__ __forceinline__ uint32_t s2u(const void* p) {
    uint32_t a;
    asm("{ .reg .u64 t; cvta.to.shared.u64 t, %1; cvt.u32.u64 %0, t; }"
        : "=r"(a) : "l"(p));
    return a;
}

__device__ __forceinline__ void cp16(uint32_t d, const void* s) {
    asm volatile("cp.async.cg.shared.global [%0], [%1], 16;" :: "r"(d), "l"(s));
}
#define CP_COMMIT() asm volatile("cp.async.commit_group;" ::: "memory")
#define CP_WAIT2()  asm volatile("cp.async.wait_group 2;" ::: "memory")

// fp16 MMA: m16n8k16, fp32 accumulate
#define MMA_F16(c, a, b)                                                      \
    asm volatile(                                                             \
        "mma.sync.aligned.m16n8k16.row.col.f32.f16.f16.f32 "                  \
        "{%0,%1,%2,%3},{%4,%5,%6,%7},{%8,%9},{%0,%1,%2,%3};"                  \
        : "+f"((c)[0]), "+f"((c)[1]), "+f"((c)[2]), "+f"((c)[3])              \
        : "r"((a)[0]), "r"((a)[1]), "r"((a)[2]), "r"((a)[3]),                 \
          "r"((b)[0]), "r"((b)[1]))

// ============================================================================
// x -> fp16
// ============================================================================
__global__ __launch_bounds__(256) void conv_x(
    const float* __restrict__ x, __half* __restrict__ Xh)
{
    const int i = blockIdx.x * 256 + threadIdx.x;
    float4 v = ((const float4*)x)[i];
    __half2 h0 = __floats2half2_rn(v.x, v.y);
    __half2 h1 = __floats2half2_rn(v.z, v.w);
    uint2 o;
    o.x = *(unsigned*)&h0;
    o.y = *(unsigned*)&h1;
    ((uint2*)Xh)[i] = o;
}

// ============================================================================
// Weight transpose + convert: Wh[z][n][k] = fp16(W_z[k][n])
// ============================================================================
__global__ __launch_bounds__(256) void trans_w(
    const float* __restrict__ W0, const float* __restrict__ W1,
    const float* __restrict__ W2, const float* __restrict__ W3,
    __half* __restrict__ Wh)
{
    __shared__ float t[32][33];
    const int z = blockIdx.z;
    const float* W = (z == 0) ? W0 : (z == 1) ? W1 : (z == 2) ? W2 : W3;
    __half* dst = Wh + (size_t)z * C_ * C_;
    const int n0 = blockIdx.x * 32;
    const int k0 = blockIdx.y * 32;
    const int tx = threadIdx.x & 31;
    const int ty = threadIdx.x >> 5;
#pragma unroll
    for (int i = 0; i < 4; ++i)
        t[ty + 8 * i][tx] = W[(k0 + ty + 8 * i) * C_ + n0 + tx];
    __syncthreads();
#pragma unroll
    for (int i = 0; i < 4; ++i)
        dst[(size_t)(n0 + ty + 8 * i) * C_ + k0 + tx] = __float2half_rn(t[tx][ty + 8 * i]);
}

// ============================================================================
// fp16 cp.async 3-stage GEMM (R14 winner, unchanged)
// ============================================================================
#define HROW 20
#define HT_WORDS (128 * HROW)
#define HGEMM_SMEM_BYTES (6 * HT_WORDS * 4)

__device__ __forceinline__ void h_issue(
    const __half* __restrict__ A, const __half* __restrict__ B,
    int K, int bm, int bn, int kb, uint32_t sbase, int stage, int tid)
{
#pragma unroll
    for (int u = 0; u < 2; ++u) {
        const int f = tid + 256 * u;
        const int row = f >> 2;
        const int ch = f & 3;
        cp16(sbase + (uint32_t)(stage * HT_WORDS + row * HROW + ch * 4) * 4,
             A + (size_t)(bm + row) * K + kb + ch * 8);
        cp16(sbase + (uint32_t)(3 * HT_WORDS + stage * HT_WORDS + row * HROW + ch * 4) * 4,
             B + (size_t)(bn + row) * K + kb + ch * 8);
    }
}

__device__ __forceinline__ void hgemm_body(
    const __half* __restrict__ A, const __half* __restrict__ B,
    float* __restrict__ Cf, __half* __restrict__ Ch, int N, int K)
{
    extern __shared__ unsigned smbuf[];
    const uint32_t sbase = s2u(smbuf);

    const int tid = threadIdx.x;
    const int bm = blockIdx.y * 128;
    const int bn = blockIdx.x * 128;

    const int wid  = tid >> 5;
    const int lane = tid & 31;
    const int g    = lane >> 2;
    const int tig  = lane & 3;
    const int warpM = wid >> 1;
    const int warpN = wid & 1;

    float c[2][8][4];
#pragma unroll
    for (int i = 0; i < 2; ++i)
#pragma unroll
        for (int j = 0; j < 8; ++j)
#pragma unroll
            for (int r = 0; r < 4; ++r) c[i][j][r] = 0.f;

    const int nt = K >> 5;

    h_issue(A, B, K, bm, bn, 0,  sbase, 0, tid); CP_COMMIT();
    h_issue(A, B, K, bm, bn, 32, sbase, 1, tid); CP_COMMIT();

    for (int t = 0; t < nt; ++t) {
        if (t + 2 < nt)
            h_issue(A, B, K, bm, bn, (t + 2) * 32, sbase, (t + 2) % 3, tid);
        CP_COMMIT();
        CP_WAIT2();
        __syncthreads();

        const unsigned* Ab = smbuf + (t % 3) * HT_WORDS;
        const unsigned* Bb = smbuf + 3 * HT_WORDS + (t % 3) * HT_WORDS;

#pragma unroll
        for (int ks = 0; ks < 2; ++ks) {
            const int k0 = ks * 8;
            unsigned a[2][4];
#pragma unroll
            for (int m2 = 0; m2 < 2; ++m2) {
                const int mr = warpM * 32 + m2 * 16;
                a[m2][0] = Ab[(mr + g) * HROW + k0 + tig];
                a[m2][1] = Ab[(mr + g + 8) * HROW + k0 + tig];
                a[m2][2] = Ab[(mr + g) * HROW + k0 + tig + 4];
                a[m2][3] = Ab[(mr + g + 8) * HROW + k0 + tig + 4];
            }
#pragma unroll
            for (int j = 0; j < 8; ++j) {
                unsigned b[2];
                const int nc = warpN * 64 + j * 8 + g;
                b[0] = Bb[nc * HROW + k0 + tig];
                b[1] = Bb[nc * HROW + k0 + tig + 4];
                MMA_F16(c[0][j], a[0], b);
                MMA_F16(c[1][j], a[1], b);
            }
        }
        __syncthreads();
    }

#pragma unroll
    for (int m2 = 0; m2 < 2; ++m2) {
#pragma unroll
        for (int j = 0; j < 8; ++j) {
            const int row = bm + warpM * 32 + m2 * 16 + g;
            const int col = bn + warpN * 64 + j * 8 + 2 * tig;
            if (Ch) {
                __half2 h0 = __floats2half2_rn(c[m2][j][0], c[m2][j][1]);
                __half2 h1 = __floats2half2_rn(c[m2][j][2], c[m2][j][3]);
                *(__half2*)&Ch[(size_t)row * N + col]       = h0;
                *(__half2*)&Ch[(size_t)(row + 8) * N + col] = h1;
            } else {
                *(float2*)&Cf[(size_t)row * N + col] =
                    make_float2(c[m2][j][0], c[m2][j][1]);
                *(float2*)&Cf[(size_t)(row + 8) * N + col] =
                    make_float2(c[m2][j][2], c[m2][j][3]);
            }
        }
    }
}

__global__ __launch_bounds__(256, 2) void hgemm_out(
    const __half* __restrict__ A, const __half* __restrict__ B,
    float* __restrict__ C)
{
    hgemm_body(A, B, C, nullptr, C_, C_);
}

__global__ __launch_bounds__(256, 2) void hgemm_qkv(
    const __half* __restrict__ A, const __half* __restrict__ W,
    __half* __restrict__ Qh, __half* __restrict__ Kh, float* __restrict__ V)
{
    const int z = blockIdx.z;
    if (z == 0)      hgemm_body(A, W,                        nullptr, Qh, C_, C_);
    else if (z == 1) hgemm_body(A, W + (size_t)C_ * C_,      nullptr, Kh, C_, C_);
    else             hgemm_body(A, W + (size_t)2 * C_ * C_,  V, nullptr, C_, C_);
}

// ============================================================================
// fp16 score row-max, 128-key tiles (2 m-atoms per warp), double-buffered
// register prefetch. Same warp layout / reduction tree as R14 winner.
// ============================================================================
__global__ __launch_bounds__(256, 2) void score_max_h(
    const __half* __restrict__ Q, const __half* __restrict__ K,
    float* __restrict__ m1)
{
    __shared__ unsigned Ks[2][128][36];   // [key][d-pair]
    __shared__ float buf[4][64];

    const int bh = blockIdx.y;
    const int b = bh >> 4, h = bh & 15;
    const int q0 = blockIdx.x * 64;
    const int tid = threadIdx.x;
    const int rowbase = (b * S_) * C_ + h * DH_;

    const int wid  = tid >> 5;
    const int lane = tid & 31;
    const int g    = lane >> 2;
    const int tig  = lane & 3;
    const int warpM = wid & 3;     // 32 key rows (2 m-atoms)
    const int warpN = wid >> 2;    // 32 queries (4 n-atoms)

    // stage Q tile (64q x 64d) into Ks[0] rows 0..63, extract B fragments
    {
#pragma unroll
        for (int u = 0; u < 2; ++u) {
            const int f = tid + 256 * u;     // 0..511 uint4 slots
            const int row = f >> 3;          // 0..63
            const int ch = f & 7;
            *(uint4*)&Ks[0][row][ch * 4] =
                *(const uint4*)(Q + rowbase + (q0 + row) * C_ + ch * 8);
        }
    }
    __syncthreads();

    unsigned bq[4][4][2];
#pragma unroll
    for (int na = 0; na < 4; ++na) {
        const int nc = warpN * 32 + na * 8 + g;
#pragma unroll
        for (int ks = 0; ks < 4; ++ks) {
            bq[na][ks][0] = Ks[0][nc][ks * 8 + tig];
            bq[na][ks][1] = Ks[0][nc][ks * 8 + tig + 4];
        }
    }
    __syncthreads();

    float rmax[4][2];
#pragma unroll
    for (int na = 0; na < 4; ++na) { rmax[na][0] = -1e30f; rmax[na][1] = -1e30f; }

    // prefetch K tile 0 (128 keys x 64 d = 1024 uint4, 4/thread)
    uint4 kv[4];
#pragma unroll
    for (int u = 0; u < 4; ++u) {
        const int f = tid + 256 * u;
        const int row = f >> 3, ch = f & 7;
        kv[u] = *(const uint4*)(K + rowbase + row * C_ + ch * 8);
    }

    const int nt = S_ / 128;   // 16
    for (int t = 0; t < nt; ++t) {
        const int cur = t & 1;
#pragma unroll
        for (int u = 0; u < 4; ++u) {
            const int f = tid + 256 * u;
            const int row = f >> 3, ch = f & 7;
            *(uint4*)&Ks[cur][row][ch * 4] = kv[u];
        }
        __syncthreads();

        if (t + 1 < nt) {
#pragma unroll
            for (int u = 0; u < 4; ++u) {
                const int f = tid + 256 * u;
                const int row = f >> 3, ch = f & 7;
                kv[u] = *(const uint4*)(K + rowbase + ((t + 1) * 128 + row) * C_ + ch * 8);
            }
        }

        float c[2][4][4];
#pragma unroll
        for (int m2 = 0; m2 < 2; ++m2)
#pragma unroll
            for (int na = 0; na < 4; ++na)
#pragma unroll
                for (int r = 0; r < 4; ++r) c[m2][na][r] = 0.f;

#pragma unroll
        for (int ks = 0; ks < 4; ++ks) {
            const int k0 = ks * 8;
            unsigned a[2][4];
#pragma unroll
            for (int m2 = 0; m2 < 2; ++m2) {
                const int mr = warpM * 32 + m2 * 16;
                a[m2][0] = Ks[cur][mr + g][k0 + tig];
                a[m2][1] = Ks[cur][mr + g + 8][k0 + tig];
                a[m2][2] = Ks[cur][mr + g][k0 + tig + 4];
                a[m2][3] = Ks[cur][mr + g + 8][k0 + tig + 4];
            }
#pragma unroll
            for (int na = 0; na < 4; ++na) {
                MMA_F16(c[0][na], a[0], bq[na][ks]);
                MMA_F16(c[1][na], a[1], bq[na][ks]);
            }
        }

#pragma unroll
        for (int m2 = 0; m2 < 2; ++m2)
#pragma unroll
            for (int na = 0; na < 4; ++na) {
                rmax[na][0] = fmaxf(rmax[na][0], fmaxf(c[m2][na][0], c[m2][na][2]));
                rmax[na][1] = fmaxf(rmax[na][1], fmaxf(c[m2][na][1], c[m2][na][3]));
            }
        __syncthreads();   // MMA reads done before next store phase
    }

#pragma unroll
    for (int off = 4; off <= 16; off <<= 1)
#pragma unroll
        for (int na = 0; na < 4; ++na) {
            rmax[na][0] = fmaxf(rmax[na][0], __shfl_xor_sync(0xffffffffu, rmax[na][0], off));
            rmax[na][1] = fmaxf(rmax[na][1], __shfl_xor_sync(0xffffffffu, rmax[na][1], off));
        }

    if (g == 0) {
#pragma unroll
        for (int na = 0; na < 4; ++na) {
            buf[warpM][warpN * 32 + na * 8 + tig * 2 + 0] = rmax[na][0];
            buf[warpM][warpN * 32 + na * 8 + tig * 2 + 1] = rmax[na][1];
        }
    }
    __syncthreads();
    if (tid < 64) {
        float m = fmaxf(fmaxf(buf[0][tid], buf[1][tid]),
                        fmaxf(buf[2][tid], buf[3][tid]));
        m1[bh * S_ + q0 + tid] = m * 0.125f;
    }
}

// ============================================================================
// V column sums, two-stage (unchanged)
// ============================================================================
__global__ __launch_bounds__(256) void vsum_part(
    const float* __restrict__ V, float* __restrict__ vsp)
{
    __shared__ float red[4][64];
    const int bh = blockIdx.x;
    const int ch = blockIdx.y;
    const int b = bh >> 4, h = bh & 15;
    const int tid = threadIdx.x;
    const int d = tid & 63, grp = tid >> 6;
    const float* p = V + (b * S_) * C_ + h * DH_ + d;
    float s = 0.f;
    for (int k = ch * 256 + grp; k < ch * 256 + 256; k += 4) s += p[k * C_];
    red[grp][d] = s;
    __syncthreads();
    if (tid < 64)
        vsp[(bh * 8 + ch) * 64 + tid] =
            red[0][tid] + red[1][tid] + red[2][tid] + red[3][tid];
}

__global__ __launch_bounds__(64) void vsum_fin(
    const float* __restrict__ vsp, float* __restrict__ vs)
{
    const int bh = blockIdx.x;
    const int tid = threadIdx.x;
    float s = 0.f;
#pragma unroll
    for (int ch = 0; ch < 8; ++ch) s += vsp[(bh * 8 + ch) * 64 + tid];
    vs[bh * 64 + tid] = s;
}

// ============================================================================
// FA2-style banded attention (R15 winner, unchanged)
// ============================================================================
__global__ __launch_bounds__(256) void band_attn_h(
    const __half* __restrict__ Q, const __half* __restrict__ K,
    const float* __restrict__ V, const float* __restrict__ m1,
    const float* __restrict__ vs, __half* __restrict__ Oh)
{
    __shared__ unsigned Qs[64][36];
    __shared__ unsigned Ks[32][36];
    __shared__ __half  Vt[64][40];
    __shared__ float   obuf[64][66];
    __shared__ float   zred[2][64];

    const int bh = blockIdx.y;
    const int b = bh >> 4, h = bh & 15;
    const int q0 = blockIdx.x * 64;
    const int tid = threadIdx.x;
    const int rowbase = (b * S_) * C_ + h * DH_;

    const int wid  = tid >> 5;
    const int lane = tid & 31;
    const int g    = lane >> 2;
    const int tig  = lane & 3;
    const int warpM = wid & 3;
    const int warpN = wid >> 2;

#pragma unroll
    for (int u = 0; u < 2; ++u) {
        const int f = tid + 256 * u;
        const int row = f >> 3;
        const int ch = f & 7;
        *(uint4*)&Qs[row][ch * 4] =
            *(const uint4*)(Q + rowbase + (q0 + row) * C_ + ch * 8);
    }
    __syncthreads();

    unsigned aq[4][4];
    const int mr = warpM * 16;
#pragma unroll
    for (int kk = 0; kk < 4; ++kk) {
        aq[kk][0] = Qs[mr + g][kk * 8 + tig];
        aq[kk][1] = Qs[mr + g + 8][kk * 8 + tig];
        aq[kk][2] = Qs[mr + g][kk * 8 + tig + 4];
        aq[kk][3] = Qs[mr + g + 8][kk * 8 + tig + 4];
    }
    float m1row[2];
    m1row[0] = m1[bh * S_ + q0 + mr + g];
    m1row[1] = m1[bh * S_ + q0 + mr + g + 8];

    float o[8][4];
#pragma unroll
    for (int na = 0; na < 8; ++na)
#pragma unroll
        for (int r = 0; r < 4; ++r) o[na][r] = 0.f;
    float zp[2] = {0.f, 0.f};

    const int klo  = (q0 >= 128) ? q0 - 128 : 0;
    const int kend = (q0 + 192 < S_) ? q0 + 192 : S_;

    for (int kt = klo; kt < kend; kt += 32) {
        __syncthreads();
        {
            const int row = tid >> 3;
            const int ch = tid & 7;
            *(uint4*)&Ks[row][ch * 4] =
                *(const uint4*)(K + rowbase + (kt + row) * C_ + ch * 8);
        }
#pragma unroll
        for (int u = 0; u < 2; ++u) {
            const int f = tid + 256 * u;
            const int r = f >> 4;
            const int c4 = (f & 15) * 4;
            float4 c = *(const float4*)(V + rowbase + (kt + r) * C_ + c4);
            Vt[c4 + 0][r] = __float2half_rn(c.x);
            Vt[c4 + 1][r] = __float2half_rn(c.y);
            Vt[c4 + 2][r] = __float2half_rn(c.z);
            Vt[c4 + 3][r] = __float2half_rn(c.w);
        }
        __syncthreads();

        float c[2][4];
#pragma unroll
        for (int na = 0; na < 2; ++na)
#pragma unroll
            for (int r = 0; r < 4; ++r) c[na][r] = 0.f;

#pragma unroll
        for (int kk = 0; kk < 4; ++kk) {
            const int k0 = kk * 8;
#pragma unroll
            for (int na = 0; na < 2; ++na) {
                unsigned bb[2];
                const int nc = warpN * 16 + na * 8 + g;
                bb[0] = Ks[nc][k0 + tig];
                bb[1] = Ks[nc][k0 + tig + 4];
                MMA_F16(c[na], aq[kk], bb);
            }
        }

        unsigned aw[4];
#pragma unroll
        for (int na = 0; na < 2; ++na) {
#pragma unroll
            for (int r2 = 0; r2 < 2; ++r2) {
                const int q = q0 + mr + g + r2 * 8;
                __half wh[2];
#pragma unroll
                for (int j = 0; j < 2; ++j) {
                    const int key = kt + warpN * 16 + na * 8 + 2 * tig + j;
                    const float sv = c[na][r2 * 2 + j];
                    const int d = key - q;
                    float tt = __expf(sv * 0.125f - m1row[r2]);
                    float w = __expf(tt) - 1.0f;
                    if (d < -128 || d > 127) w = 0.f;
                    wh[j] = __float2half_rn(w);
                    zp[r2] += __half2float(wh[j]);
                }
                __half2 p = __halves2half2(wh[0], wh[1]);
                aw[na * 2 + r2] = *(unsigned*)&p;
            }
        }
        unsigned afrag[4] = { aw[0], aw[1], aw[2], aw[3] };

#pragma unroll
        for (int na = 0; na < 8; ++na) {
            unsigned bv[2];
            const int nc2 = na * 8 + g;
            const unsigned* vw = (const unsigned*)&Vt[nc2][0];
            bv[0] = vw[warpN * 8 + tig];
            bv[1] = vw[warpN * 8 + tig + 4];
            MMA_F16(o[na], afrag, bv);
        }
    }

#pragma unroll
    for (int off = 1; off <= 2; off <<= 1) {
        zp[0] += __shfl_xor_sync(0xffffffffu, zp[0], off);
        zp[1] += __shfl_xor_sync(0xffffffffu, zp[1], off);
    }
    if (tig == 0) {
        zred[warpN][mr + g]     = zp[0];
        zred[warpN][mr + g + 8] = zp[1];
    }

    __syncthreads();
    if (warpN == 0) {
#pragma unroll
        for (int na = 0; na < 8; ++na) {
            const int col = na * 8 + 2 * tig;
            *(float2*)&obuf[mr + g][col]     = make_float2(o[na][0], o[na][1]);
            *(float2*)&obuf[mr + g + 8][col] = make_float2(o[na][2], o[na][3]);
        }
    }
    __syncthreads();
    if (warpN == 1) {
        const float* vsp = vs + bh * 64;
#pragma unroll
        for (int r2 = 0; r2 < 2; ++r2) {
            const int row = mr + g + r2 * 8;
            const float inv = 1.0f / ((float)S_ + zred[0][row] + zred[1][row]);
            __half* op = Oh + rowbase + (q0 + row) * C_;
#pragma unroll
            for (int na = 0; na < 8; ++na) {
                const int col = na * 8 + 2 * tig;
                float v0 = (o[na][r2 * 2 + 0] + obuf[row][col]     + vsp[col])     * inv;
                float v1 = (o[na][r2 * 2 + 1] + obuf[row][col + 1] + vsp[col + 1]) * inv;
                *(__half2*)(op + col) = __floats2half2_rn(v0, v1);
            }
        }
    }
}

// ============================================================================
extern "C" void kernel_launch(void* const* d_in, const int* in_sizes, int n_in,
                              void* d_out, int out_size)
{
    (void)in_sizes; (void)n_in; (void)out_size;
    const float* x  = (const float*)d_in[0];
    const float* Wq = (const float*)d_in[1];
    const float* Wk = (const float*)d_in[2];
    const float* Wv = (const float*)d_in[3];
    const float* Wo = (const float*)d_in[4];
    float* out = (float*)d_out;

    __half *Qhp, *Khp, *Ahp, *Xhp, *Whp;
    float *Vp, *m1p, *vsp, *vspp;
    cudaGetSymbolAddress((void**)&Qhp, g_Qh);
    cudaGetSymbolAddress((void**)&Khp, g_Kh);
    cudaGetSymbolAddress((void**)&Vp,  g_V);
    cudaGetSymbolAddress((void**)&Ahp, g_Ah);
    cudaGetSymbolAddress((void**)&Xhp, g_Xh);
    cudaGetSymbolAddress((void**)&Whp, g_Wh);
    cudaGetSymbolAddress((void**)&m1p, g_m1);
    cudaGetSymbolAddress((void**)&vsp, g_vs);
    cudaGetSymbolAddress((void**)&vspp, g_vsp);

    cudaFuncSetAttribute(hgemm_out,
                         cudaFuncAttributeMaxDynamicSharedMemorySize,
                         HGEMM_SMEM_BYTES);
    cudaFuncSetAttribute(hgemm_qkv,
                         cudaFuncAttributeMaxDynamicSharedMemorySize,
                         HGEMM_SMEM_BYTES);

    conv_x<<<(M_ * C_ / 4) / 256, 256>>>(x, Xhp);
    trans_w<<<dim3(32, 32, 4), 256>>>(Wq, Wk, Wv, Wo, Whp);

    dim3 gq(C_ / 128, M_ / 128, 3);         // (8, 32, 3)
    hgemm_qkv<<<gq, 256, HGEMM_SMEM_BYTES>>>(Xhp, Whp, Qhp, Khp, Vp);

    score_max_h<<<dim3(S_ / 64, B_ * H_), 256>>>(Qhp, Khp, m1p);
    vsum_part<<<dim3(B_ * H_, 8), 256>>>(Vp, vspp);
    vsum_fin<<<B_ * H_, 64>>>(vspp, vsp);
    band_attn_h<<<dim3(S_ / 64, B_ * H_), 256>>>(Qhp, Khp, Vp, m1p, vsp, Ahp);

    dim3 gg(C_ / 128, M_ / 128);            // (8, 32)
    hgemm_out<<<gg, 256, HGEMM_SMEM_BYTES>>>(Ahp, Whp + (size_t)3 * C_ * C_, out);
}

// round 17
// speedup vs baseline: 1.9868x; 1.0545x over previous
#include <cuda_runtime.h>
#include <cuda_fp16.h>
#include <math.h>
#include <cstdint>

#define B_   2
#define S_   2048
#define C_   1024
#define H_   16
#define DH_  64
#define M_   (B_ * S_)       // 4096 rows

// ---- scratch (device globals; no allocation allowed) ----
__device__ __half g_Qh[M_ * C_];         // fp16 Q (GEMM epilogue)
__device__ __half g_Kh[M_ * C_];         // fp16 K
__device__ float  g_V [M_ * C_];         // exact fp32 V
__device__ __half g_Ah[M_ * C_];         // fp16 attention output
__device__ __half g_Xh[M_ * C_];         // fp16 x
__device__ __half g_Wh[4 * C_ * C_];     // fp16 weights, TRANSPOSED [z][N][K]
__device__ float  g_m1[B_ * H_ * S_];
__device__ float  g_vs[B_ * H_ * DH_];
__device__ float  g_vsp[B_ * H_ * 8 * DH_];

__device__ __forceinline__ uint32_t s2u(const void* p) {
    uint32_t a;
    asm("{ .reg .u64 t; cvta.to.shared.u64 t, %1; cvt.u32.u64 %0, t; }"
        : "=r"(a) : "l"(p));
    return a;
}

__device__ __forceinline__ void cp16(uint32_t d, const void* s) {
    asm volatile("cp.async.cg.shared.global [%0], [%1], 16;" :: "r"(d), "l"(s));
}
#define CP_COMMIT() asm volatile("cp.async.commit_group;" ::: "memory")
#define CP_WAIT2()  asm volatile("cp.async.wait_group 2;" ::: "memory")

// fp16 MMA: m16n8k16, fp32 accumulate
#define MMA_F16(c, a, b)                                                      \
    asm volatile(                                                             \
        "mma.sync.aligned.m16n8k16.row.col.f32.f16.f16.f32 "                  \
        "{%0,%1,%2,%3},{%4,%5,%6,%7},{%8,%9},{%0,%1,%2,%3};"                  \
        : "+f"((c)[0]), "+f"((c)[1]), "+f"((c)[2]), "+f"((c)[3])              \
        : "r"((a)[0]), "r"((a)[1]), "r"((a)[2]), "r"((a)[3]),                 \
          "r"((b)[0]), "r"((b)[1]))

// ldmatrix x4 (non-transposed, b16)
#define LDSM4(r, addr)                                                        \
    asm volatile("ldmatrix.sync.aligned.m8n8.x4.shared.b16 {%0,%1,%2,%3}, [%4];" \
        : "=r"((r)[0]), "=r"((r)[1]), "=r"((r)[2]), "=r"((r)[3]) : "r"(addr))

// ============================================================================
// x -> fp16
// ============================================================================
__global__ __launch_bounds__(256) void conv_x(
    const float* __restrict__ x, __half* __restrict__ Xh)
{
    const int i = blockIdx.x * 256 + threadIdx.x;
    float4 v = ((const float4*)x)[i];
    __half2 h0 = __floats2half2_rn(v.x, v.y);
    __half2 h1 = __floats2half2_rn(v.z, v.w);
    uint2 o;
    o.x = *(unsigned*)&h0;
    o.y = *(unsigned*)&h1;
    ((uint2*)Xh)[i] = o;
}

// ============================================================================
// Weight transpose + convert: Wh[z][n][k] = fp16(W_z[k][n])
// ============================================================================
__global__ __launch_bounds__(256) void trans_w(
    const float* __restrict__ W0, const float* __restrict__ W1,
    const float* __restrict__ W2, const float* __restrict__ W3,
    __half* __restrict__ Wh)
{
    __shared__ float t[32][33];
    const int z = blockIdx.z;
    const float* W = (z == 0) ? W0 : (z == 1) ? W1 : (z == 2) ? W2 : W3;
    __half* dst = Wh + (size_t)z * C_ * C_;
    const int n0 = blockIdx.x * 32;
    const int k0 = blockIdx.y * 32;
    const int tx = threadIdx.x & 31;
    const int ty = threadIdx.x >> 5;
#pragma unroll
    for (int i = 0; i < 4; ++i)
        t[ty + 8 * i][tx] = W[(k0 + ty + 8 * i) * C_ + n0 + tx];
    __syncthreads();
#pragma unroll
    for (int i = 0; i < 4; ++i)
        dst[(size_t)(n0 + ty + 8 * i) * C_ + k0 + tx] = __float2half_rn(t[tx][ty + 8 * i]);
}

// ============================================================================
// fp16 cp.async 3-stage GEMM with ldmatrix fragment loads.
// ============================================================================
#define HROW 20
#define HT_WORDS (128 * HROW)
#define HGEMM_SMEM_BYTES (6 * HT_WORDS * 4)

__device__ __forceinline__ void h_issue(
    const __half* __restrict__ A, const __half* __restrict__ B,
    int K, int bm, int bn, int kb, uint32_t sbase, int stage, int tid)
{
#pragma unroll
    for (int u = 0; u < 2; ++u) {
        const int f = tid + 256 * u;
        const int row = f >> 2;
        const int ch = f & 3;
        cp16(sbase + (uint32_t)(stage * HT_WORDS + row * HROW + ch * 4) * 4,
             A + (size_t)(bm + row) * K + kb + ch * 8);
        cp16(sbase + (uint32_t)(3 * HT_WORDS + stage * HT_WORDS + row * HROW + ch * 4) * 4,
             B + (size_t)(bn + row) * K + kb + ch * 8);
    }
}

__device__ __forceinline__ void hgemm_body(
    const __half* __restrict__ A, const __half* __restrict__ B,
    float* __restrict__ Cf, __half* __restrict__ Ch, int N, int K)
{
    extern __shared__ unsigned smbuf[];
    const uint32_t sbase = s2u(smbuf);

    const int tid = threadIdx.x;
    const int bm = blockIdx.y * 128;
    const int bn = blockIdx.x * 128;

    const int wid  = tid >> 5;
    const int lane = tid & 31;
    const int g    = lane >> 2;
    const int tig  = lane & 3;
    const int warpM = wid >> 1;
    const int warpN = wid & 1;

    // ldmatrix per-lane base offsets (bytes within a stage)
    const int lane15 = lane & 15;
    uint32_t a_off[2];
#pragma unroll
    for (int m2 = 0; m2 < 2; ++m2)
        a_off[m2] = (uint32_t)((warpM * 32 + m2 * 16 + lane15) * HROW
                               + (lane >> 4) * 4) * 4;
    uint32_t b_off[4];
#pragma unroll
    for (int jj = 0; jj < 4; ++jj)
        b_off[jj] = (uint32_t)((warpN * 64 + jj * 16 + (lane >> 4) * 8 + (lane & 7)) * HROW
                               + ((lane >> 3) & 1) * 4) * 4;

    float c[2][8][4];
#pragma unroll
    for (int i = 0; i < 2; ++i)
#pragma unroll
        for (int j = 0; j < 8; ++j)
#pragma unroll
            for (int r = 0; r < 4; ++r) c[i][j][r] = 0.f;

    const int nt = K >> 5;

    h_issue(A, B, K, bm, bn, 0,  sbase, 0, tid); CP_COMMIT();
    h_issue(A, B, K, bm, bn, 32, sbase, 1, tid); CP_COMMIT();

    for (int t = 0; t < nt; ++t) {
        if (t + 2 < nt)
            h_issue(A, B, K, bm, bn, (t + 2) * 32, sbase, (t + 2) % 3, tid);
        CP_COMMIT();
        CP_WAIT2();
        __syncthreads();

        const uint32_t Ab_s = sbase + (uint32_t)((t % 3) * HT_WORDS) * 4;
        const uint32_t Bb_s = sbase + (uint32_t)((3 + t % 3) * HT_WORDS) * 4;

#pragma unroll
        for (int ks = 0; ks < 2; ++ks) {
            const uint32_t kofs = ks * 32;   // 8 words
            unsigned a[2][4];
            LDSM4(a[0], Ab_s + a_off[0] + kofs);
            LDSM4(a[1], Ab_s + a_off[1] + kofs);
#pragma unroll
            for (int jj = 0; jj < 4; ++jj) {
                unsigned b4[4];
                LDSM4(b4, Bb_s + b_off[jj] + kofs);
                MMA_F16(c[0][jj * 2 + 0], a[0], (b4 + 0));
                MMA_F16(c[1][jj * 2 + 0], a[1], (b4 + 0));
                MMA_F16(c[0][jj * 2 + 1], a[0], (b4 + 2));
                MMA_F16(c[1][jj * 2 + 1], a[1], (b4 + 2));
            }
        }
        __syncthreads();
    }

#pragma unroll
    for (int m2 = 0; m2 < 2; ++m2) {
#pragma unroll
        for (int j = 0; j < 8; ++j) {
            const int row = bm + warpM * 32 + m2 * 16 + g;
            const int col = bn + warpN * 64 + j * 8 + 2 * tig;
            if (Ch) {
                __half2 h0 = __floats2half2_rn(c[m2][j][0], c[m2][j][1]);
                __half2 h1 = __floats2half2_rn(c[m2][j][2], c[m2][j][3]);
                *(__half2*)&Ch[(size_t)row * N + col]       = h0;
                *(__half2*)&Ch[(size_t)(row + 8) * N + col] = h1;
            } else {
                *(float2*)&Cf[(size_t)row * N + col] =
                    make_float2(c[m2][j][0], c[m2][j][1]);
                *(float2*)&Cf[(size_t)(row + 8) * N + col] =
                    make_float2(c[m2][j][2], c[m2][j][3]);
            }
        }
    }
}

__global__ __launch_bounds__(256, 2) void hgemm_out(
    const __half* __restrict__ A, const __half* __restrict__ B,
    float* __restrict__ C)
{
    hgemm_body(A, B, C, nullptr, C_, C_);
}

__global__ __launch_bounds__(256, 2) void hgemm_qkv(
    const __half* __restrict__ A, const __half* __restrict__ W,
    __half* __restrict__ Qh, __half* __restrict__ Kh, float* __restrict__ V)
{
    const int z = blockIdx.z;
    if (z == 0)      hgemm_body(A, W,                        nullptr, Qh, C_, C_);
    else if (z == 1) hgemm_body(A, W + (size_t)C_ * C_,      nullptr, Kh, C_, C_);
    else             hgemm_body(A, W + (size_t)2 * C_ * C_,  V, nullptr, C_, C_);
}

// ============================================================================
// fp16 score row-max, 128-key tiles + ldmatrix A-fragment loads.
// ============================================================================
__global__ __launch_bounds__(256, 2) void score_max_h(
    const __half* __restrict__ Q, const __half* __restrict__ K,
    float* __restrict__ m1)
{
    __shared__ unsigned Ks[2][128][36];   // [key][d-pair], 144B rows
    __shared__ float buf[4][64];

    const int bh = blockIdx.y;
    const int b = bh >> 4, h = bh & 15;
    const int q0 = blockIdx.x * 64;
    const int tid = threadIdx.x;
    const int rowbase = (b * S_) * C_ + h * DH_;
    const uint32_t ksb = s2u(Ks);

    const int wid  = tid >> 5;
    const int lane = tid & 31;
    const int g    = lane >> 2;
    const int tig  = lane & 3;
    const int warpM = wid & 3;     // 32 key rows (2 m-atoms)
    const int warpN = wid >> 2;    // 32 queries (4 n-atoms)

    const int lane15 = lane & 15;
    uint32_t a_off[2];
#pragma unroll
    for (int m2 = 0; m2 < 2; ++m2)
        a_off[m2] = (uint32_t)((warpM * 32 + m2 * 16 + lane15) * 36
                               + (lane >> 4) * 4) * 4;
    const uint32_t stage_bytes = 128 * 36 * 4;

    // stage Q tile (64q x 64d) into Ks[0] rows 0..63, extract B fragments
    {
#pragma unroll
        for (int u = 0; u < 2; ++u) {
            const int f = tid + 256 * u;
            const int row = f >> 3;
            const int ch = f & 7;
            *(uint4*)&Ks[0][row][ch * 4] =
                *(const uint4*)(Q + rowbase + (q0 + row) * C_ + ch * 8);
        }
    }
    __syncthreads();

    unsigned bq[4][4][2];
#pragma unroll
    for (int na = 0; na < 4; ++na) {
        const int nc = warpN * 32 + na * 8 + g;
#pragma unroll
        for (int ks = 0; ks < 4; ++ks) {
            bq[na][ks][0] = Ks[0][nc][ks * 8 + tig];
            bq[na][ks][1] = Ks[0][nc][ks * 8 + tig + 4];
        }
    }
    __syncthreads();

    float rmax[4][2];
#pragma unroll
    for (int na = 0; na < 4; ++na) { rmax[na][0] = -1e30f; rmax[na][1] = -1e30f; }

    uint4 kv[4];
#pragma unroll
    for (int u = 0; u < 4; ++u) {
        const int f = tid + 256 * u;
        const int row = f >> 3, ch = f & 7;
        kv[u] = *(const uint4*)(K + rowbase + row * C_ + ch * 8);
    }

    const int nt = S_ / 128;   // 16
    for (int t = 0; t < nt; ++t) {
        const int cur = t & 1;
#pragma unroll
        for (int u = 0; u < 4; ++u) {
            const int f = tid + 256 * u;
            const int row = f >> 3, ch = f & 7;
            *(uint4*)&Ks[cur][row][ch * 4] = kv[u];
        }
        __syncthreads();

        if (t + 1 < nt) {
#pragma unroll
            for (int u = 0; u < 4; ++u) {
                const int f = tid + 256 * u;
                const int row = f >> 3, ch = f & 7;
                kv[u] = *(const uint4*)(K + rowbase + ((t + 1) * 128 + row) * C_ + ch * 8);
            }
        }

        float c[2][4][4];
#pragma unroll
        for (int m2 = 0; m2 < 2; ++m2)
#pragma unroll
            for (int na = 0; na < 4; ++na)
#pragma unroll
                for (int r = 0; r < 4; ++r) c[m2][na][r] = 0.f;

        const uint32_t base = ksb + cur * stage_bytes;
#pragma unroll
        for (int ks = 0; ks < 4; ++ks) {
            const uint32_t kofs = ks * 32;
            unsigned a[2][4];
            LDSM4(a[0], base + a_off[0] + kofs);
            LDSM4(a[1], base + a_off[1] + kofs);
#pragma unroll
            for (int na = 0; na < 4; ++na) {
                MMA_F16(c[0][na], a[0], bq[na][ks]);
                MMA_F16(c[1][na], a[1], bq[na][ks]);
            }
        }

#pragma unroll
        for (int m2 = 0; m2 < 2; ++m2)
#pragma unroll
            for (int na = 0; na < 4; ++na) {
                rmax[na][0] = fmaxf(rmax[na][0], fmaxf(c[m2][na][0], c[m2][na][2]));
                rmax[na][1] = fmaxf(rmax[na][1], fmaxf(c[m2][na][1], c[m2][na][3]));
            }
        __syncthreads();
    }

#pragma unroll
    for (int off = 4; off <= 16; off <<= 1)
#pragma unroll
        for (int na = 0; na < 4; ++na) {
            rmax[na][0] = fmaxf(rmax[na][0], __shfl_xor_sync(0xffffffffu, rmax[na][0], off));
            rmax[na][1] = fmaxf(rmax[na][1], __shfl_xor_sync(0xffffffffu, rmax[na][1], off));
        }

    if (g == 0) {
#pragma unroll
        for (int na = 0; na < 4; ++na) {
            buf[warpM][warpN * 32 + na * 8 + tig * 2 + 0] = rmax[na][0];
            buf[warpM][warpN * 32 + na * 8 + tig * 2 + 1] = rmax[na][1];
        }
    }
    __syncthreads();
    if (tid < 64) {
        float m = fmaxf(fmaxf(buf[0][tid], buf[1][tid]),
                        fmaxf(buf[2][tid], buf[3][tid]));
        m1[bh * S_ + q0 + tid] = m * 0.125f;
    }
}

// ============================================================================
// V column sums, two-stage (unchanged)
// ============================================================================
__global__ __launch_bounds__(256) void vsum_part(
    const float* __restrict__ V, float* __restrict__ vsp)
{
    __shared__ float red[4][64];
    const int bh = blockIdx.x;
    const int ch = blockIdx.y;
    const int b = bh >> 4, h = bh & 15;
    const int tid = threadIdx.x;
    const int d = tid & 63, grp = tid >> 6;
    const float* p = V + (b * S_) * C_ + h * DH_ + d;
    float s = 0.f;
    for (int k = ch * 256 + grp; k < ch * 256 + 256; k += 4) s += p[k * C_];
    red[grp][d] = s;
    __syncthreads();
    if (tid < 64)
        vsp[(bh * 8 + ch) * 64 + tid] =
            red[0][tid] + red[1][tid] + red[2][tid] + red[3][tid];
}

__global__ __launch_bounds__(64) void vsum_fin(
    const float* __restrict__ vsp, float* __restrict__ vs)
{
    const int bh = blockIdx.x;
    const int tid = threadIdx.x;
    float s = 0.f;
#pragma unroll
    for (int ch = 0; ch < 8; ++ch) s += vsp[(bh * 8 + ch) * 64 + tid];
    vs[bh * 64 + tid] = s;
}

// ============================================================================
// FA2-style banded attention (R15/R16 winner, unchanged)
// ============================================================================
__global__ __launch_bounds__(256) void band_attn_h(
    const __half* __restrict__ Q, const __half* __restrict__ K,
    const float* __restrict__ V, const float* __restrict__ m1,
    const float* __restrict__ vs, __half* __restrict__ Oh)
{
    __shared__ unsigned Qs[64][36];
    __shared__ unsigned Ks[32][36];
    __shared__ __half  Vt[64][40];
    __shared__ float   obuf[64][66];
    __shared__ float   zred[2][64];

    const int bh = blockIdx.y;
    const int b = bh >> 4, h = bh & 15;
    const int q0 = blockIdx.x * 64;
    const int tid = threadIdx.x;
    const int rowbase = (b * S_) * C_ + h * DH_;

    const int wid  = tid >> 5;
    const int lane = tid & 31;
    const int g    = lane >> 2;
    const int tig  = lane & 3;
    const int warpM = wid & 3;
    const int warpN = wid >> 2;

#pragma unroll
    for (int u = 0; u < 2; ++u) {
        const int f = tid + 256 * u;
        const int row = f >> 3;
        const int ch = f & 7;
        *(uint4*)&Qs[row][ch * 4] =
            *(const uint4*)(Q + rowbase + (q0 + row) * C_ + ch * 8);
    }
    __syncthreads();

    unsigned aq[4][4];
    const int mr = warpM * 16;
#pragma unroll
    for (int kk = 0; kk < 4; ++kk) {
        aq[kk][0] = Qs[mr + g][kk * 8 + tig];
        aq[kk][1] = Qs[mr + g + 8][kk * 8 + tig];
        aq[kk][2] = Qs[mr + g][kk * 8 + tig + 4];
        aq[kk][3] = Qs[mr + g + 8][kk * 8 + tig + 4];
    }
    float m1row[2];
    m1row[0] = m1[bh * S_ + q0 + mr + g];
    m1row[1] = m1[bh * S_ + q0 + mr + g + 8];

    float o[8][4];
#pragma unroll
    for (int na = 0; na < 8; ++na)
#pragma unroll
        for (int r = 0; r < 4; ++r) o[na][r] = 0.f;
    float zp[2] = {0.f, 0.f};

    const int klo  = (q0 >= 128) ? q0 - 128 : 0;
    const int kend = (q0 + 192 < S_) ? q0 + 192 : S_;

    for (int kt = klo; kt < kend; kt += 32) {
        __syncthreads();
        {
            const int row = tid >> 3;
            const int ch = tid & 7;
            *(uint4*)&Ks[row][ch * 4] =
                *(const uint4*)(K + rowbase + (kt + row) * C_ + ch * 8);
        }
#pragma unroll
        for (int u = 0; u < 2; ++u) {
            const int f = tid + 256 * u;
            const int r = f >> 4;
            const int c4 = (f & 15) * 4;
            float4 c = *(const float4*)(V + rowbase + (kt + r) * C_ + c4);
            Vt[c4 + 0][r] = __float2half_rn(c.x);
            Vt[c4 + 1][r] = __float2half_rn(c.y);
            Vt[c4 + 2][r] = __float2half_rn(c.z);
            Vt[c4 + 3][r] = __float2half_rn(c.w);
        }
        __syncthreads();

        float c[2][4];
#pragma unroll
        for (int na = 0; na < 2; ++na)
#pragma unroll
            for (int r = 0; r < 4; ++r) c[na][r] = 0.f;

#pragma unroll
        for (int kk = 0; kk < 4; ++kk) {
            const int k0 = kk * 8;
#pragma unroll
            for (int na = 0; na < 2; ++na) {
                unsigned bb[2];
                const int nc = warpN * 16 + na * 8 + g;
                bb[0] = Ks[nc][k0 + tig];
                bb[1] = Ks[nc][k0 + tig + 4];
                MMA_F16(c[na], aq[kk], bb);
            }
        }

        unsigned aw[4];
#pragma unroll
        for (int na = 0; na < 2; ++na) {
#pragma unroll
            for (int r2 = 0; r2 < 2; ++r2) {
                const int q = q0 + mr + g + r2 * 8;
                __half wh[2];
#pragma unroll
                for (int j = 0; j < 2; ++j) {
                    const int key = kt + warpN * 16 + na * 8 + 2 * tig + j;
                    const float sv = c[na][r2 * 2 + j];
                    const int d = key - q;
                    float tt = __expf(sv * 0.125f - m1row[r2]);
                    float w = __expf(tt) - 1.0f;
                    if (d < -128 || d > 127) w = 0.f;
                    wh[j] = __float2half_rn(w);
                    zp[r2] += __half2float(wh[j]);
                }
                __half2 p = __halves2half2(wh[0], wh[1]);
                aw[na * 2 + r2] = *(unsigned*)&p;
            }
        }
        unsigned afrag[4] = { aw[0], aw[1], aw[2], aw[3] };

#pragma unroll
        for (int na = 0; na < 8; ++na) {
            unsigned bv[2];
            const int nc2 = na * 8 + g;
            const unsigned* vw = (const unsigned*)&Vt[nc2][0];
            bv[0] = vw[warpN * 8 + tig];
            bv[1] = vw[warpN * 8 + tig + 4];
            MMA_F16(o[na], afrag, bv);
        }
    }

#pragma unroll
    for (int off = 1; off <= 2; off <<= 1) {
        zp[0] += __shfl_xor_sync(0xffffffffu, zp[0], off);
        zp[1] += __shfl_xor_sync(0xffffffffu, zp[1], off);
    }
    if (tig == 0) {
        zred[warpN][mr + g]     = zp[0];
        zred[warpN][mr + g + 8] = zp[1];
    }

    __syncthreads();
    if (warpN == 0) {
#pragma unroll
        for (int na = 0; na < 8; ++na) {
            const int col = na * 8 + 2 * tig;
            *(float2*)&obuf[mr + g][col]     = make_float2(o[na][0], o[na][1]);
            *(float2*)&obuf[mr + g + 8][col] = make_float2(o[na][2], o[na][3]);
        }
    }
    __syncthreads();
    if (warpN == 1) {
        const float* vsp = vs + bh * 64;
#pragma unroll
        for (int r2 = 0; r2 < 2; ++r2) {
            const int row = mr + g + r2 * 8;
            const float inv = 1.0f / ((float)S_ + zred[0][row] + zred[1][row]);
            __half* op = Oh + rowbase + (q0 + row) * C_;
#pragma unroll
            for (int na = 0; na < 8; ++na) {
                const int col = na * 8 + 2 * tig;
                float v0 = (o[na][r2 * 2 + 0] + obuf[row][col]     + vsp[col])     * inv;
                float v1 = (o[na][r2 * 2 + 1] + obuf[row][col + 1] + vsp[col + 1]) * inv;
                *(__half2*)(op + col) = __floats2half2_rn(v0, v1);
            }
        }
    }
}

// ============================================================================
extern "C" void kernel_launch(void* const* d_in, const int* in_sizes, int n_in,
                              void* d_out, int out_size)
{
    (void)in_sizes; (void)n_in; (void)out_size;
    const float* x  = (const float*)d_in[0];
    const float* Wq = (const float*)d_in[1];
    const float* Wk = (const float*)d_in[2];
    const float* Wv = (const float*)d_in[3];
    const float* Wo = (const float*)d_in[4];
    float* out = (float*)d_out;

    __half *Qhp, *Khp, *Ahp, *Xhp, *Whp;
    float *Vp, *m1p, *vsp, *vspp;
    cudaGetSymbolAddress((void**)&Qhp, g_Qh);
    cudaGetSymbolAddress((void**)&Khp, g_Kh);
    cudaGetSymbolAddress((void**)&Vp,  g_V);
    cudaGetSymbolAddress((void**)&Ahp, g_Ah);
    cudaGetSymbolAddress((void**)&Xhp, g_Xh);
    cudaGetSymbolAddress((void**)&Whp, g_Wh);
    cudaGetSymbolAddress((void**)&m1p, g_m1);
    cudaGetSymbolAddress((void**)&vsp, g_vs);
    cudaGetSymbolAddress((void**)&vspp, g_vsp);

    cudaFuncSetAttribute(hgemm_out,
                         cudaFuncAttributeMaxDynamicSharedMemorySize,
                         HGEMM_SMEM_BYTES);
    cudaFuncSetAttribute(hgemm_qkv,
                         cudaFuncAttributeMaxDynamicSharedMemorySize,
                         HGEMM_SMEM_BYTES);

    conv_x<<<(M_ * C_ / 4) / 256, 256>>>(x, Xhp);
    trans_w<<<dim3(32, 32, 4), 256>>>(Wq, Wk, Wv, Wo, Whp);

    dim3 gq(C_ / 128, M_ / 128, 3);         // (8, 32, 3)
    hgemm_qkv<<<gq, 256, HGEMM_SMEM_BYTES>>>(Xhp, Whp, Qhp, Khp, Vp);

    score_max_h<<<dim3(S_ / 64, B_ * H_), 256>>>(Qhp, Khp, m1p);
    vsum_part<<<dim3(B_ * H_, 8), 256>>>(Vp, vspp);
    vsum_fin<<<B_ * H_, 64>>>(vspp, vsp);
    band_attn_h<<<dim3(S_ / 64, B_ * H_), 256>>>(Qhp, Khp, Vp, m1p, vsp, Ahp);

    dim3 gg(C_ / 128, M_ / 128);            // (8, 32)
    hgemm_out<<<gg, 256, HGEMM_SMEM_BYTES>>>(Ahp, Whp + (size_t)3 * C_ * C_, out);
}